// round 2
// baseline (speedup 1.0000x reference)
#include <cuda_runtime.h>
#include <math.h>
#include <stdint.h>

// Problem dims
#define B_   128
#define L_   400
#define S_   30
#define V_   50000
#define EMB_ 128
#define H_   512
#define M_   512
#define OOV_ 30
#define VX_  (V_ + OOV_)   // 50030

// ---------------- output layout (floats), reference return-tuple order ----------------
#define OFF_FINAL 0                          // [B, V+OOV]
#define OFF_H     (B_*VX_)                   // [1,B,H]
#define OFF_WCTX  (OFF_H + B_*H_)            // [B,M]
#define OFF_ATTN  (OFF_WCTX + B_*M_)         // [B,L]
#define OFF_PGEN  (OFF_ATTN + B_*L_)         // [B,1]
#define OFF_COV   (OFF_PGEN + B_)            // [B,L]

// ---------------- scratch layout (floats) ----------------
#define O_YEMB    0                                   // B*EMB
#define O_GI      (O_YEMB + B_*EMB_)                  // B*3H
#define O_GH      (O_GI + B_*3*H_)                    // B*3H
#define O_HLAST   (O_GH + B_*3*H_)                    // B*H
#define O_DECW    (O_HLAST + B_*H_)                   // B*H
#define O_DECS    (O_DECW + B_*H_)                    // B*H
#define O_PARTW   (O_DECS + B_*H_)                    // 4*B*L (per-column-tile score partials)
#define O_PARTS   (O_PARTW + 4*B_*L_)                 // 4*B*S
#define O_ATTNS   (O_PARTS + 4*B_*S_)                 // B*S
#define O_CAT     (O_ATTNS + B_*S_)                   // B*3H  [wctx|sctx|h_last]
#define O_HID     (O_CAT + B_*3*H_)                   // B*H
#define O_LOGITS  (O_HID + B_*H_)                     // B*V
#define O_VMAX    (O_LOGITS + (size_t)B_*V_)          // B
#define O_VSUM    (O_VMAX + B_)                       // B
#define O_PGEN    (O_VSUM + B_)                       // B
#define SCRATCH_FLOATS (O_PGEN + B_)

__device__ __align__(256) float g_scratch[SCRATCH_FLOATS];

// =====================================================================
// Generic fp32 GEMM:  C[M,N] = A[M,K] * B[N,K]^T (+ bias[N])
// A row-major [M,K], B row-major [N,K]. M multiple of 128, K multiple of 8.
// 128x128 block tile, BK=8, 256 threads, 8x8 micro-tile.
// =====================================================================
__global__ __launch_bounds__(256)
void sgemm_tn(const float* __restrict__ A, const float* __restrict__ Bm,
              const float* __restrict__ bias, float* __restrict__ C,
              int M, int N, int K) {
    __shared__ float As[8][128];
    __shared__ float Bs[8][128];
    const int bm = blockIdx.y * 128;
    const int bn = blockIdx.x * 128;
    const int tid = threadIdx.x;
    const int tx = tid & 15;
    const int ty = tid >> 4;
    const int lrow = tid >> 1;
    const int lk4  = (tid & 1) * 4;

    float acc[8][8];
#pragma unroll
    for (int i = 0; i < 8; i++)
#pragma unroll
        for (int j = 0; j < 8; j++) acc[i][j] = 0.f;

    const float* Aptr = A + (size_t)(bm + lrow) * K + lk4;
    const bool bvalid = (bn + lrow) < N;
    const float* Bptr = Bm + (size_t)(bvalid ? (bn + lrow) : 0) * K + lk4;

    for (int k0 = 0; k0 < K; k0 += 8) {
        float4 a4 = *reinterpret_cast<const float4*>(Aptr + k0);
        float4 b4 = bvalid ? *reinterpret_cast<const float4*>(Bptr + k0)
                           : make_float4(0.f, 0.f, 0.f, 0.f);
        As[lk4 + 0][lrow] = a4.x; As[lk4 + 1][lrow] = a4.y;
        As[lk4 + 2][lrow] = a4.z; As[lk4 + 3][lrow] = a4.w;
        Bs[lk4 + 0][lrow] = b4.x; Bs[lk4 + 1][lrow] = b4.y;
        Bs[lk4 + 2][lrow] = b4.z; Bs[lk4 + 3][lrow] = b4.w;
        __syncthreads();
#pragma unroll
        for (int kk = 0; kk < 8; kk++) {
            float af[8], bf[8];
#pragma unroll
            for (int i = 0; i < 8; i++) af[i] = As[kk][ty * 8 + i];
#pragma unroll
            for (int j = 0; j < 8; j++) bf[j] = Bs[kk][tx * 8 + j];
#pragma unroll
            for (int i = 0; i < 8; i++)
#pragma unroll
                for (int j = 0; j < 8; j++) acc[i][j] += af[i] * bf[j];
        }
        __syncthreads();
    }

#pragma unroll
    for (int i = 0; i < 8; i++) {
        int row = bm + ty * 8 + i;
#pragma unroll
        for (int j = 0; j < 8; j++) {
            int col = bn + tx * 8 + j;
            if (col < N)
                C[(size_t)row * N + col] = acc[i][j] + (bias ? bias[col] : 0.f);
        }
    }
}

// =====================================================================
// Fused feature-GEMM + attention-score epilogue.
// feat = mem[total,512] @ proj[512,512]^T  (never materialized)
// partial[cb*total + row] = sum over this 128-col tile of v[d]*tanh(feat + dec[b,d] + cov[row]*covproj[d])
// Deterministic: each (row, column-tile) partial written by exactly one thread.
// total multiple of 128; K = N = 512.
// =====================================================================
__global__ __launch_bounds__(256)
void feat_score_k(const float* __restrict__ A, const float* __restrict__ Bm,
                  const float* __restrict__ dec, const float* __restrict__ cov,
                  const float* __restrict__ covproj, const float* __restrict__ v,
                  float* __restrict__ partial, int total, int Lrow) {
    __shared__ float As[8][128];
    __shared__ float Bs[8][128];
    const int bm = blockIdx.y * 128;
    const int bn = blockIdx.x * 128;           // column tile (d-range)
    const int tid = threadIdx.x;
    const int tx = tid & 15;
    const int ty = tid >> 4;
    const int lrow = tid >> 1;
    const int lk4  = (tid & 1) * 4;

    float acc[8][8];
#pragma unroll
    for (int i = 0; i < 8; i++)
#pragma unroll
        for (int j = 0; j < 8; j++) acc[i][j] = 0.f;

    const float* Aptr = A + (size_t)(bm + lrow) * 512 + lk4;
    const float* Bptr = Bm + (size_t)(bn + lrow) * 512 + lk4;

    for (int k0 = 0; k0 < 512; k0 += 8) {
        float4 a4 = *reinterpret_cast<const float4*>(Aptr + k0);
        float4 b4 = *reinterpret_cast<const float4*>(Bptr + k0);
        As[lk4 + 0][lrow] = a4.x; As[lk4 + 1][lrow] = a4.y;
        As[lk4 + 2][lrow] = a4.z; As[lk4 + 3][lrow] = a4.w;
        Bs[lk4 + 0][lrow] = b4.x; Bs[lk4 + 1][lrow] = b4.y;
        Bs[lk4 + 2][lrow] = b4.z; Bs[lk4 + 3][lrow] = b4.w;
        __syncthreads();
#pragma unroll
        for (int kk = 0; kk < 8; kk++) {
            float af[8], bf[8];
#pragma unroll
            for (int i = 0; i < 8; i++) af[i] = As[kk][ty * 8 + i];
#pragma unroll
            for (int j = 0; j < 8; j++) bf[j] = Bs[kk][tx * 8 + j];
#pragma unroll
            for (int i = 0; i < 8; i++)
#pragma unroll
                for (int j = 0; j < 8; j++) acc[i][j] += af[i] * bf[j];
        }
        __syncthreads();
    }

    // epilogue: per-thread columns bn + tx*8 + j
    float vj[8], cpj[8];
#pragma unroll
    for (int j = 0; j < 8; j++) {
        int col = bn + tx * 8 + j;
        vj[j]  = v[col];
        cpj[j] = covproj ? covproj[col] : 0.f;
    }
#pragma unroll
    for (int i = 0; i < 8; i++) {
        int row = bm + ty * 8 + i;
        int b = row / Lrow;
        float c = cov ? cov[row] : 0.f;
        const float* db = dec + b * 512 + bn + tx * 8;
        float s = 0.f;
#pragma unroll
        for (int j = 0; j < 8; j++) {
            float x = acc[i][j] + db[j] + c * cpj[j];
            s += vj[j] * tanhf(x);
        }
        // reduce across the 16 tx lanes of this ty group (contiguous in warp)
#pragma unroll
        for (int o = 8; o > 0; o >>= 1) s += __shfl_xor_sync(0xffffffffu, s, o);
        if (tx == 0) partial[(size_t)blockIdx.x * total + row] = s;
    }
}

// =====================================================================
// Small kernels
// =====================================================================
__global__ void embed_k(const int* __restrict__ y, const float* __restrict__ emb) {
    int b = blockIdx.x, t = threadIdx.x;
    g_scratch[O_YEMB + b * EMB_ + t] = emb[(size_t)y[b] * EMB_ + t];
}

__global__ void gru_gate_k(const float* __restrict__ h_prev, float* __restrict__ out) {
    int idx = blockIdx.x * blockDim.x + threadIdx.x;   // B*H
    int b = idx / H_, d = idx % H_;
    const float* gi = g_scratch + O_GI + b * 3 * H_;
    const float* gh = g_scratch + O_GH + b * 3 * H_;
    float r = 1.f / (1.f + expf(-(gi[d] + gh[d])));
    float z = 1.f / (1.f + expf(-(gi[H_ + d] + gh[H_ + d])));
    float n = tanhf(gi[2 * H_ + d] + r * gh[2 * H_ + d]);
    float hp = h_prev[b * H_ + d];
    float hl = (1.f - z) * n + z * hp;
    g_scratch[O_HLAST + b * H_ + d] = hl;
    g_scratch[O_CAT + b * 3 * H_ + 2 * H_ + d] = hl;  // cat = [wctx|sctx|h_last]
    out[OFF_H + b * H_ + d] = hl;
}

// masked softmax exactly as reference: softmax -> *mask -> renorm(+1e-10); also cov out
// scores come in as 4 column-tile partials.
__global__ void word_softmax_k(const float* __restrict__ mask,
                               const float* __restrict__ cov_in,
                               float* __restrict__ out) {
    __shared__ float sh[512];
    int b = blockIdx.x, t = threadIdx.x;
    int idx = b * L_ + t;
    float s = -1e30f;
    if (t < L_) {
        s = g_scratch[O_PARTW + idx] + g_scratch[O_PARTW + B_ * L_ + idx]
          + g_scratch[O_PARTW + 2 * B_ * L_ + idx] + g_scratch[O_PARTW + 3 * B_ * L_ + idx];
    }
    sh[t] = s; __syncthreads();
    for (int o = 256; o > 0; o >>= 1) { if (t < o) sh[t] = fmaxf(sh[t], sh[t + o]); __syncthreads(); }
    float mx = sh[0]; __syncthreads();
    float e = (t < L_) ? expf(s - mx) : 0.f;
    sh[t] = e; __syncthreads();
    for (int o = 256; o > 0; o >>= 1) { if (t < o) sh[t] += sh[t + o]; __syncthreads(); }
    float sum = sh[0]; __syncthreads();
    float am = (t < L_) ? (e / sum) * mask[b * L_ + t] : 0.f;
    sh[t] = am; __syncthreads();
    for (int o = 256; o > 0; o >>= 1) { if (t < o) sh[t] += sh[t + o]; __syncthreads(); }
    float sum2 = sh[0];
    if (t < L_) {
        float a = am / (sum2 + 1e-10f);
        out[OFF_ATTN + b * L_ + t] = a;
        out[OFF_COV + b * L_ + t]  = cov_in[b * L_ + t] + a;
    }
}

__global__ void sent_softmax_k(const float* __restrict__ mask) {
    int b = blockIdx.x, t = threadIdx.x;  // 32 threads
    int idx = b * S_ + t;
    float s = -1e30f;
    if (t < S_) {
        s = g_scratch[O_PARTS + idx] + g_scratch[O_PARTS + B_ * S_ + idx]
          + g_scratch[O_PARTS + 2 * B_ * S_ + idx] + g_scratch[O_PARTS + 3 * B_ * S_ + idx];
    }
    float mx = s;
#pragma unroll
    for (int o = 16; o > 0; o >>= 1) mx = fmaxf(mx, __shfl_xor_sync(0xffffffffu, mx, o));
    float e = (t < S_) ? expf(s - mx) : 0.f;
    float sum = e;
#pragma unroll
    for (int o = 16; o > 0; o >>= 1) sum += __shfl_xor_sync(0xffffffffu, sum, o);
    float am = (t < S_) ? (e / sum) * mask[b * S_ + t] : 0.f;
    float sum2 = am;
#pragma unroll
    for (int o = 16; o > 0; o >>= 1) sum2 += __shfl_xor_sync(0xffffffffu, sum2, o);
    if (t < S_) g_scratch[O_ATTNS + b * S_ + t] = am / (sum2 + 1e-10f);
}

__global__ void word_ctx_k(const float* __restrict__ mem, float* __restrict__ out) {
    __shared__ float sa[L_];
    int b = blockIdx.x, t = threadIdx.x;   // 512
    if (t < L_) sa[t] = out[OFF_ATTN + b * L_ + t];
    __syncthreads();
    float acc = 0.f;
    const float* mb = mem + (size_t)b * L_ * M_ + t;
#pragma unroll 4
    for (int l = 0; l < L_; l++) acc += sa[l] * mb[(size_t)l * M_];
    out[OFF_WCTX + b * M_ + t] = acc;
    g_scratch[O_CAT + b * 3 * H_ + t] = acc;
}

__global__ void sent_ctx_k(const float* __restrict__ mem) {
    __shared__ float sa[S_];
    int b = blockIdx.x, t = threadIdx.x;   // 512
    if (t < S_) sa[t] = g_scratch[O_ATTNS + b * S_ + t];
    __syncthreads();
    float acc = 0.f;
    const float* mb = mem + (size_t)b * S_ * M_ + t;
#pragma unroll 5
    for (int l = 0; l < S_; l++) acc += sa[l] * mb[(size_t)l * M_];
    g_scratch[O_CAT + b * 3 * H_ + H_ + t] = acc;
}

__global__ void pgen_k(const float* __restrict__ pw, const float* __restrict__ pb,
                       float* __restrict__ out) {
    __shared__ float sh[256];
    int b = blockIdx.x, t = threadIdx.x;
    float s = 0.f;
    for (int i = t; i < EMB_ + 3 * H_; i += 256) {   // 1664 = [wctx|sctx|h_last|y_emb]
        float x = (i < 3 * H_) ? g_scratch[O_CAT + b * 3 * H_ + i]
                               : g_scratch[O_YEMB + b * EMB_ + (i - 3 * H_)];
        s += pw[i] * x;
    }
    sh[t] = s; __syncthreads();
    for (int o = 128; o > 0; o >>= 1) { if (t < o) sh[t] += sh[t + o]; __syncthreads(); }
    if (t == 0) {
        float p = 1.f / (1.f + expf(-(sh[0] + pb[0])));
        g_scratch[O_PGEN + b] = p;
        out[OFF_PGEN + b] = p;
    }
}

__global__ void vocab_stats_k() {
    __shared__ float sh[1024];
    int b = blockIdx.x, t = threadIdx.x;
    const float* lg = g_scratch + O_LOGITS + (size_t)b * V_;
    float m = -1e30f;
    for (int v = t; v < V_; v += 1024) m = fmaxf(m, lg[v]);
    sh[t] = m; __syncthreads();
    for (int o = 512; o > 0; o >>= 1) { if (t < o) sh[t] = fmaxf(sh[t], sh[t + o]); __syncthreads(); }
    float mx = sh[0]; __syncthreads();
    float s = 0.f;
    for (int v = t; v < V_; v += 1024) s += expf(lg[v] - mx);
    sh[t] = s; __syncthreads();
    for (int o = 512; o > 0; o >>= 1) { if (t < o) sh[t] += sh[t + o]; __syncthreads(); }
    if (t == 0) { g_scratch[O_VMAX + b] = mx; g_scratch[O_VSUM + b] = sh[0]; }
}

__global__ void assemble_k(float* __restrict__ out) {
    int b = blockIdx.y;
    int v = blockIdx.x * 1024 + threadIdx.x;
    if (v >= VX_) return;
    float r;
    if (v < V_) {
        float p = g_scratch[O_PGEN + b];
        r = p * expf(g_scratch[O_LOGITS + (size_t)b * V_ + v] - g_scratch[O_VMAX + b])
              / g_scratch[O_VSUM + b];
    } else {
        r = 0.f;
    }
    out[(size_t)b * VX_ + v] = r;
}

__global__ void scatter_k(const int* __restrict__ src_oov, float* __restrict__ out) {
    int idx = blockIdx.x * 256 + threadIdx.x;   // B*L
    if (idx >= B_ * L_) return;
    int b = idx / L_;
    float val = (1.f - g_scratch[O_PGEN + b]) * out[OFF_ATTN + idx];
    atomicAdd(&out[(size_t)b * VX_ + src_oov[idx]], val);
}

// =====================================================================
extern "C" void kernel_launch(void* const* d_in, const int* in_sizes, int n_in,
                              void* d_out, int out_size) {
    const float* h_in      = (const float*)d_in[0];
    const float* wmem      = (const float*)d_in[1];
    const float* smem      = (const float*)d_in[2];
    const float* wmask     = (const float*)d_in[3];
    const float* smask     = (const float*)d_in[4];
    const float* coverage  = (const float*)d_in[5];
    const float* emb       = (const float*)d_in[6];
    const float* gru_w_ih  = (const float*)d_in[7];
    const float* gru_w_hh  = (const float*)d_in[8];
    const float* gru_b_ih  = (const float*)d_in[9];
    const float* gru_b_hh  = (const float*)d_in[10];
    const float* w_mem_proj= (const float*)d_in[11];
    const float* w_dec_w   = (const float*)d_in[12];
    const float* w_dec_b   = (const float*)d_in[13];
    const float* w_v       = (const float*)d_in[14];
    const float* w_covp    = (const float*)d_in[15];
    const float* s_mem_proj= (const float*)d_in[16];
    const float* s_dec_w   = (const float*)d_in[17];
    const float* s_dec_b   = (const float*)d_in[18];
    const float* s_v       = (const float*)d_in[19];
    const float* pgen_w    = (const float*)d_in[20];
    const float* pgen_b    = (const float*)d_in[21];
    const float* vd1_w     = (const float*)d_in[22];
    const float* vd1_b     = (const float*)d_in[23];
    const float* vd2_w     = (const float*)d_in[24];
    const float* vd2_b     = (const float*)d_in[25];
    const int*   y         = (const int*)d_in[26];
    const int*   src_oov   = (const int*)d_in[27];
    float* out = (float*)d_out;

    float* sp = nullptr;
    cudaGetSymbolAddress((void**)&sp, g_scratch);

    // 1. embedding gather
    embed_k<<<B_, EMB_>>>(y, emb);
    // 2/3. GRU input & hidden GEMMs: [B,3H]
    sgemm_tn<<<dim3(12, 1), 256>>>(sp + O_YEMB, gru_w_ih, gru_b_ih, sp + O_GI, B_, 3 * H_, EMB_);
    sgemm_tn<<<dim3(12, 1), 256>>>(h_in,        gru_w_hh, gru_b_hh, sp + O_GH, B_, 3 * H_, H_);
    // 4. GRU gates -> h_last (+ h_next out, cat slot)
    gru_gate_k<<<(B_ * H_) / 256, 256>>>(h_in, out);
    // 5/6. decoder projections (with bias)
    sgemm_tn<<<dim3(4, 1), 256>>>(sp + O_HLAST, w_dec_w, w_dec_b, sp + O_DECW, B_, H_, H_);
    sgemm_tn<<<dim3(4, 1), 256>>>(sp + O_HLAST, s_dec_w, s_dec_b, sp + O_DECS, B_, H_, H_);
    // 7/8. fused feature GEMM + score epilogue (feat never materialized)
    feat_score_k<<<dim3(4, (B_ * L_) / 128), 256>>>(wmem, w_mem_proj, sp + O_DECW,
                                                    coverage, w_covp, w_v,
                                                    sp + O_PARTW, B_ * L_, L_);
    feat_score_k<<<dim3(4, (B_ * S_) / 128), 256>>>(smem, s_mem_proj, sp + O_DECS,
                                                    nullptr, nullptr, s_v,
                                                    sp + O_PARTS, B_ * S_, S_);
    // 9/10. masked softmaxes (word also writes attn + new coverage outputs)
    word_softmax_k<<<B_, 512>>>(wmask, coverage, out);
    sent_softmax_k<<<B_, 32>>>(smask);
    // 11/12. contexts
    word_ctx_k<<<B_, 512>>>(wmem, out);
    sent_ctx_k<<<B_, 512>>>(smem);
    // 13. hid = cat([wctx,sctx,h_last]) @ vd1_w^T + b
    sgemm_tn<<<dim3(4, 1), 256>>>(sp + O_CAT, vd1_w, vd1_b, sp + O_HID, B_, H_, 3 * H_);
    // 14. vocab logits
    sgemm_tn<<<dim3((V_ + 127) / 128, 1), 256>>>(sp + O_HID, vd2_w, vd2_b, sp + O_LOGITS, B_, V_, H_);
    // 15. row max/sum for vocab softmax
    vocab_stats_k<<<B_, 1024>>>();
    // 16. p_gen
    pgen_k<<<B_, 256>>>(pgen_w, pgen_b, out);
    // 17. final_dist = p_gen*softmax(logits), zeros for OOV slots
    assemble_k<<<dim3((VX_ + 1023) / 1024, B_), 1024>>>(out);
    // 18. scatter-add copy distribution
    scatter_k<<<(B_ * L_ + 255) / 256, 256>>>(src_oov, out);
}

// round 4
// speedup vs baseline: 1.4209x; 1.4209x over previous
#include <cuda_runtime.h>
#include <cuda_bf16.h>
#include <math.h>
#include <stdint.h>

// Problem dims
#define B_   128
#define L_   400
#define S_   30
#define V_   50000
#define EMB_ 128
#define H_   512
#define M_   512
#define OOV_ 30
#define VX_  (V_ + OOV_)   // 50030

// ---------------- output layout (floats), reference return-tuple order ----------------
#define OFF_FINAL 0                          // [B, V+OOV]
#define OFF_H     (B_*VX_)                   // [1,B,H]
#define OFF_WCTX  (OFF_H + B_*H_)            // [B,M]
#define OFF_ATTN  (OFF_WCTX + B_*M_)         // [B,L]
#define OFF_PGEN  (OFF_ATTN + B_*L_)         // [B,1]
#define OFF_COV   (OFF_PGEN + B_)            // [B,L]

// ---------------- scratch layout (floats) ----------------
#define O_YEMB    0
#define O_GI      (O_YEMB + B_*EMB_)
#define O_GH      (O_GI + B_*3*H_)
#define O_HLAST   (O_GH + B_*3*H_)
#define O_DECW    (O_HLAST + B_*H_)
#define O_DECS    (O_DECW + B_*H_)
#define O_PARTW   (O_DECS + B_*H_)            // 4*B*L score partials
#define O_PARTS   (O_PARTW + 4*B_*L_)         // 4*B*S
#define O_ATTNS   (O_PARTS + 4*B_*S_)
#define O_CAT     (O_ATTNS + B_*S_)           // B*3H [wctx|sctx|h_last]
#define O_HID     (O_CAT + B_*3*H_)
#define O_LOGITS  (O_HID + B_*H_)             // B*V
#define O_VMAX    (O_LOGITS + (size_t)B_*V_)
#define O_VSUM    (O_VMAX + B_)
#define O_PGEN    (O_VSUM + B_)
#define SCRATCH_FLOATS (O_PGEN + B_)

__device__ __align__(256) float g_scratch[SCRATCH_FLOATS];

// ===================== HMMA helpers (mma.sync, baseline sm_80+ PTX) =====================
__device__ __forceinline__ uint32_t smem_u32(const void* p) {
    uint32_t a;
    asm("{ .reg .u64 t; cvta.to.shared.u64 t, %1; cvt.u32.u64 %0, t; }" : "=r"(a) : "l"(p));
    return a;
}

__device__ __forceinline__ void ldm4(uint32_t* r, uint32_t addr) {
    asm volatile("ldmatrix.sync.aligned.m8n8.x4.shared.b16 {%0,%1,%2,%3}, [%4];"
                 : "=r"(r[0]), "=r"(r[1]), "=r"(r[2]), "=r"(r[3]) : "r"(addr));
}

__device__ __forceinline__ void mma16816(float* c, const uint32_t* a, const uint32_t* b) {
    asm volatile("mma.sync.aligned.m16n8k16.row.col.f32.bf16.bf16.f32 "
                 "{%0,%1,%2,%3}, {%4,%5,%6,%7}, {%8,%9}, {%0,%1,%2,%3};"
                 : "+f"(c[0]), "+f"(c[1]), "+f"(c[2]), "+f"(c[3])
                 : "r"(a[0]), "r"(a[1]), "r"(a[2]), "r"(a[3]), "r"(b[0]), "r"(b[1]));
}

// smem tile layout: padded rows of 72 bf16 (144 B) -> conflict-free ldmatrix
#define PADK 72
#define RB   144            // row bytes
#define GEMM_SMEM 73728     // 4 tiles * 128 * 144
#define A_HI 0
#define A_LO 18432
#define B_HI 36864
#define B_LO 55296

// convert float4 -> bf16 hi/lo (3-term split operands), store 8B each
__device__ __forceinline__ void cvt_store4p(char* hi, char* lo, uint32_t off, float4 x) {
    __nv_bfloat16 h0 = __float2bfloat16(x.x), h1 = __float2bfloat16(x.y);
    __nv_bfloat16 h2 = __float2bfloat16(x.z), h3 = __float2bfloat16(x.w);
    __nv_bfloat16 l0 = __float2bfloat16(x.x - __bfloat162float(h0));
    __nv_bfloat16 l1 = __float2bfloat16(x.y - __bfloat162float(h1));
    __nv_bfloat16 l2 = __float2bfloat16(x.z - __bfloat162float(h2));
    __nv_bfloat16 l3 = __float2bfloat16(x.w - __bfloat162float(h3));
    uint32_t hA = (uint32_t)__bfloat16_as_ushort(h0) | ((uint32_t)__bfloat16_as_ushort(h1) << 16);
    uint32_t hB = (uint32_t)__bfloat16_as_ushort(h2) | ((uint32_t)__bfloat16_as_ushort(h3) << 16);
    uint32_t lA = (uint32_t)__bfloat16_as_ushort(l0) | ((uint32_t)__bfloat16_as_ushort(l1) << 16);
    uint32_t lB = (uint32_t)__bfloat16_as_ushort(l2) | ((uint32_t)__bfloat16_as_ushort(l3) << 16);
    *(uint32_t*)(hi + off)     = hA;
    *(uint32_t*)(hi + off + 4) = hB;
    *(uint32_t*)(lo + off)     = lA;
    *(uint32_t*)(lo + off + 4) = lB;
}

// =====================================================================
// Fused HMMA feature-GEMM + attention-score epilogue.
// feat = A[total,512] @ Bm[512,512]^T (bf16 3-term, fp32 accum, never materialized)
// partial[nb*total+row] = sum over this 128-col slice of v[d]*tanh(feat+dec[b,d]+cov*covproj[d])
// grid = (4, total/128); block = 256 (8 warps: wm 0-3 x wn 0-1, warp tile 32x64)
// =====================================================================
__global__ __launch_bounds__(256)
void feat_score_mma(const float* __restrict__ A, const float* __restrict__ Bm,
                    const float* __restrict__ dec, const float* __restrict__ cov,
                    const float* __restrict__ covproj, const float* __restrict__ v,
                    float* __restrict__ partial, int total, int Lrow) {
    extern __shared__ char smem[];
    __shared__ float sv[128], scp[128], spart[2][128];
    const uint32_t sb = smem_u32(smem);
    const int tid = threadIdx.x;
    const int lane = tid & 31, wid = tid >> 5;
    const int wm = wid & 3, wn = wid >> 2;
    const int bm = blockIdx.y * 128;
    const int nb = blockIdx.x;              // 128-col slice

    if (tid < 128) {
        sv[tid]  = v[nb * 128 + tid];
        scp[tid] = covproj ? covproj[nb * 128 + tid] : 0.f;
    }

    float acc[2][8][4];
#pragma unroll
    for (int mt = 0; mt < 2; mt++)
#pragma unroll
        for (int nt = 0; nt < 8; nt++)
#pragma unroll
            for (int e = 0; e < 4; e++) acc[mt][nt][e] = 0.f;

    // precomputed ldmatrix smem addresses (k-invariant part)
    const uint32_t a_row = (uint32_t)(wm * 32 + (lane & 15));
    const uint32_t a_koff = (uint32_t)((lane >> 4) * 16);      // bytes
    const uint32_t b_row0 = (uint32_t)(wn * 64 + ((lane >> 4) & 1) * 8 + (lane & 7));
    const uint32_t b_koff = (uint32_t)(((lane >> 3) & 1) * 16); // bytes

    for (int ch = 0; ch < 8; ch++) {
        __syncthreads();
        // A chunk: 128 rows x 64 k
        for (int i = tid; i < 2048; i += 256) {
            int r = i >> 4, c4 = i & 15;
            float4 x = *(const float4*)(A + (size_t)(bm + r) * 512 + ch * 64 + c4 * 4);
            cvt_store4p(smem + A_HI, smem + A_LO, (uint32_t)(r * RB + c4 * 8), x);
        }
        // B chunk: this CTA's 128 proj rows x 64 k
        for (int i = tid; i < 2048; i += 256) {
            int r = i >> 4, c4 = i & 15;
            float4 x = *(const float4*)(Bm + (size_t)(nb * 128 + r) * 512 + ch * 64 + c4 * 4);
            cvt_store4p(smem + B_HI, smem + B_LO, (uint32_t)(r * RB + c4 * 8), x);
        }
        __syncthreads();
#pragma unroll
        for (int ks = 0; ks < 4; ks++) {
            uint32_t ah[2][4], al[2][4], bh[4][4], bl[4][4];
#pragma unroll
            for (int mt = 0; mt < 2; mt++) {
                uint32_t off = (a_row + mt * 16) * RB + ks * 32 + a_koff;
                ldm4(ah[mt], sb + A_HI + off);
                ldm4(al[mt], sb + A_LO + off);
            }
#pragma unroll
            for (int ng = 0; ng < 4; ng++) {
                uint32_t off = (b_row0 + ng * 16) * RB + ks * 32 + b_koff;
                ldm4(bh[ng], sb + B_HI + off);
                ldm4(bl[ng], sb + B_LO + off);
            }
#pragma unroll
            for (int mt = 0; mt < 2; mt++)
#pragma unroll
                for (int ng = 0; ng < 4; ng++) {
                    mma16816(acc[mt][2 * ng],     ah[mt], &bh[ng][0]);
                    mma16816(acc[mt][2 * ng + 1], ah[mt], &bh[ng][2]);
                    mma16816(acc[mt][2 * ng],     ah[mt], &bl[ng][0]);
                    mma16816(acc[mt][2 * ng + 1], ah[mt], &bl[ng][2]);
                    mma16816(acc[mt][2 * ng],     al[mt], &bh[ng][0]);
                    mma16816(acc[mt][2 * ng + 1], al[mt], &bh[ng][2]);
                }
        }
    }

    // epilogue: per-row partial score over this 128-col slice
    const int g = lane >> 2, t4 = lane & 3;
#pragma unroll
    for (int mt = 0; mt < 2; mt++)
#pragma unroll
        for (int h = 0; h < 2; h++) {
            int rl = wm * 32 + mt * 16 + h * 8 + g;
            int row = bm + rl;
            int b = row / Lrow;
            float c = cov ? cov[row] : 0.f;
            const float* db = dec + (size_t)b * 512 + nb * 128;
            float s = 0.f;
#pragma unroll
            for (int nt = 0; nt < 8; nt++)
#pragma unroll
                for (int e = 0; e < 2; e++) {
                    int cl = wn * 64 + nt * 8 + t4 * 2 + e;
                    float x = acc[mt][nt][h * 2 + e] + db[cl] + c * scp[cl];
                    s += sv[cl] * tanhf(x);
                }
            s += __shfl_xor_sync(0xffffffffu, s, 1);
            s += __shfl_xor_sync(0xffffffffu, s, 2);
            if (t4 == 0) spart[wn][rl] = s;
        }
    __syncthreads();
    if (tid < 128)
        partial[(size_t)nb * total + bm + tid] = spart[0][tid] + spart[1][tid];
}

// =====================================================================
// HMMA vocab-logits GEMM: logits[b, v] = hid[b,:] . W[v,:] + bias[v]
// grid.x = ceil(V/128) over W rows; N = 128 batch. Epilogue: smem transpose.
// =====================================================================
__global__ __launch_bounds__(256)
void vd2_mma(const float* __restrict__ W, const float* __restrict__ hid,
             const float* __restrict__ bias, float* __restrict__ logits) {
    extern __shared__ char smem[];
    const uint32_t sb = smem_u32(smem);
    const int tid = threadIdx.x;
    const int lane = tid & 31, wid = tid >> 5;
    const int wm = wid & 3, wn = wid >> 2;
    const int bm = blockIdx.x * 128;

    float acc[2][8][4];
#pragma unroll
    for (int mt = 0; mt < 2; mt++)
#pragma unroll
        for (int nt = 0; nt < 8; nt++)
#pragma unroll
            for (int e = 0; e < 4; e++) acc[mt][nt][e] = 0.f;

    const uint32_t a_row = (uint32_t)(wm * 32 + (lane & 15));
    const uint32_t a_koff = (uint32_t)((lane >> 4) * 16);
    const uint32_t b_row0 = (uint32_t)(wn * 64 + ((lane >> 4) & 1) * 8 + (lane & 7));
    const uint32_t b_koff = (uint32_t)(((lane >> 3) & 1) * 16);

    for (int ch = 0; ch < 8; ch++) {
        __syncthreads();
        for (int i = tid; i < 2048; i += 256) {       // A: W rows (clamped tail)
            int r = i >> 4, c4 = i & 15;
            int rg = bm + r; if (rg >= V_) rg = V_ - 1;
            float4 x = *(const float4*)(W + (size_t)rg * 512 + ch * 64 + c4 * 4);
            cvt_store4p(smem + A_HI, smem + A_LO, (uint32_t)(r * RB + c4 * 8), x);
        }
        for (int i = tid; i < 2048; i += 256) {       // B: hid [128,512]
            int r = i >> 4, c4 = i & 15;
            float4 x = *(const float4*)(hid + (size_t)r * 512 + ch * 64 + c4 * 4);
            cvt_store4p(smem + B_HI, smem + B_LO, (uint32_t)(r * RB + c4 * 8), x);
        }
        __syncthreads();
#pragma unroll
        for (int ks = 0; ks < 4; ks++) {
            uint32_t ah[2][4], al[2][4], bh[4][4], bl[4][4];
#pragma unroll
            for (int mt = 0; mt < 2; mt++) {
                uint32_t off = (a_row + mt * 16) * RB + ks * 32 + a_koff;
                ldm4(ah[mt], sb + A_HI + off);
                ldm4(al[mt], sb + A_LO + off);
            }
#pragma unroll
            for (int ng = 0; ng < 4; ng++) {
                uint32_t off = (b_row0 + ng * 16) * RB + ks * 32 + b_koff;
                ldm4(bh[ng], sb + B_HI + off);
                ldm4(bl[ng], sb + B_LO + off);
            }
#pragma unroll
            for (int mt = 0; mt < 2; mt++)
#pragma unroll
                for (int ng = 0; ng < 4; ng++) {
                    mma16816(acc[mt][2 * ng],     ah[mt], &bh[ng][0]);
                    mma16816(acc[mt][2 * ng + 1], ah[mt], &bh[ng][2]);
                    mma16816(acc[mt][2 * ng],     ah[mt], &bl[ng][0]);
                    mma16816(acc[mt][2 * ng + 1], ah[mt], &bl[ng][2]);
                    mma16816(acc[mt][2 * ng],     al[mt], &bh[ng][0]);
                    mma16816(acc[mt][2 * ng + 1], al[mt], &bh[ng][2]);
                }
        }
    }

    // epilogue: transpose via padded smem (pad 133 -> conflict-free read)
    __syncthreads();
    float* tr = (float*)smem;   // 128*133*4 = 68096 <= 73728
    const int g = lane >> 2, t4 = lane & 3;
#pragma unroll
    for (int mt = 0; mt < 2; mt++)
#pragma unroll
        for (int h = 0; h < 2; h++) {
            int vl = wm * 32 + mt * 16 + h * 8 + g;
            int vg = bm + vl; int vc = vg < V_ ? vg : V_ - 1;
            float bia = bias[vc];
#pragma unroll
            for (int nt = 0; nt < 8; nt++)
#pragma unroll
                for (int e = 0; e < 2; e++) {
                    int cb = wn * 64 + nt * 8 + t4 * 2 + e;
                    tr[vl * 133 + cb] = acc[mt][nt][h * 2 + e] + bia;
                }
        }
    __syncthreads();
    for (int i = tid; i < 16384; i += 256) {
        int b = i >> 7, vl = i & 127;
        int vg = bm + vl;
        if (vg < V_) logits[(size_t)b * V_ + vg] = tr[vl * 133 + b];
    }
}

// =====================================================================
// SIMT fp32 GEMM for the small layers: C[M,N] = A[M,K]*B[N,K]^T (+bias)
// =====================================================================
__global__ __launch_bounds__(256)
void sgemm_tn(const float* __restrict__ A, const float* __restrict__ Bm,
              const float* __restrict__ bias, float* __restrict__ C,
              int M, int N, int K) {
    __shared__ float As[8][128];
    __shared__ float Bs[8][128];
    const int bm = blockIdx.y * 128;
    const int bn = blockIdx.x * 128;
    const int tid = threadIdx.x;
    const int tx = tid & 15, ty = tid >> 4;
    const int lrow = tid >> 1, lk4 = (tid & 1) * 4;

    float acc[8][8];
#pragma unroll
    for (int i = 0; i < 8; i++)
#pragma unroll
        for (int j = 0; j < 8; j++) acc[i][j] = 0.f;

    const float* Aptr = A + (size_t)(bm + lrow) * K + lk4;
    const bool bvalid = (bn + lrow) < N;
    const float* Bptr = Bm + (size_t)(bvalid ? (bn + lrow) : 0) * K + lk4;

    for (int k0 = 0; k0 < K; k0 += 8) {
        float4 a4 = *reinterpret_cast<const float4*>(Aptr + k0);
        float4 b4 = bvalid ? *reinterpret_cast<const float4*>(Bptr + k0)
                           : make_float4(0.f, 0.f, 0.f, 0.f);
        As[lk4 + 0][lrow] = a4.x; As[lk4 + 1][lrow] = a4.y;
        As[lk4 + 2][lrow] = a4.z; As[lk4 + 3][lrow] = a4.w;
        Bs[lk4 + 0][lrow] = b4.x; Bs[lk4 + 1][lrow] = b4.y;
        Bs[lk4 + 2][lrow] = b4.z; Bs[lk4 + 3][lrow] = b4.w;
        __syncthreads();
#pragma unroll
        for (int kk = 0; kk < 8; kk++) {
            float af[8], bf[8];
#pragma unroll
            for (int i = 0; i < 8; i++) af[i] = As[kk][ty * 8 + i];
#pragma unroll
            for (int j = 0; j < 8; j++) bf[j] = Bs[kk][tx * 8 + j];
#pragma unroll
            for (int i = 0; i < 8; i++)
#pragma unroll
                for (int j = 0; j < 8; j++) acc[i][j] += af[i] * bf[j];
        }
        __syncthreads();
    }
#pragma unroll
    for (int i = 0; i < 8; i++) {
        int row = bm + ty * 8 + i;
#pragma unroll
        for (int j = 0; j < 8; j++) {
            int col = bn + tx * 8 + j;
            if (col < N) C[(size_t)row * N + col] = acc[i][j] + (bias ? bias[col] : 0.f);
        }
    }
}

// =====================================================================
// Small kernels
// =====================================================================
__global__ void embed_k(const int* __restrict__ y, const float* __restrict__ emb) {
    int b = blockIdx.x, t = threadIdx.x;
    g_scratch[O_YEMB + b * EMB_ + t] = emb[(size_t)y[b] * EMB_ + t];
}

__global__ void gru_gate_k(const float* __restrict__ h_prev, float* __restrict__ out) {
    int idx = blockIdx.x * blockDim.x + threadIdx.x;
    int b = idx / H_, d = idx % H_;
    const float* gi = g_scratch + O_GI + b * 3 * H_;
    const float* gh = g_scratch + O_GH + b * 3 * H_;
    float r = 1.f / (1.f + expf(-(gi[d] + gh[d])));
    float z = 1.f / (1.f + expf(-(gi[H_ + d] + gh[H_ + d])));
    float n = tanhf(gi[2 * H_ + d] + r * gh[2 * H_ + d]);
    float hp = h_prev[b * H_ + d];
    float hl = (1.f - z) * n + z * hp;
    g_scratch[O_HLAST + b * H_ + d] = hl;
    g_scratch[O_CAT + b * 3 * H_ + 2 * H_ + d] = hl;
    out[OFF_H + b * H_ + d] = hl;
}

__global__ void word_softmax_k(const float* __restrict__ mask,
                               const float* __restrict__ cov_in,
                               float* __restrict__ out) {
    __shared__ float sh[512];
    int b = blockIdx.x, t = threadIdx.x;
    int idx = b * L_ + t;
    float s = -1e30f;
    if (t < L_) {
        s = g_scratch[O_PARTW + idx] + g_scratch[O_PARTW + B_ * L_ + idx]
          + g_scratch[O_PARTW + 2 * B_ * L_ + idx] + g_scratch[O_PARTW + 3 * B_ * L_ + idx];
    }
    sh[t] = s; __syncthreads();
    for (int o = 256; o > 0; o >>= 1) { if (t < o) sh[t] = fmaxf(sh[t], sh[t + o]); __syncthreads(); }
    float mx = sh[0]; __syncthreads();
    float e = (t < L_) ? expf(s - mx) : 0.f;
    sh[t] = e; __syncthreads();
    for (int o = 256; o > 0; o >>= 1) { if (t < o) sh[t] += sh[t + o]; __syncthreads(); }
    float sum = sh[0]; __syncthreads();
    float am = (t < L_) ? (e / sum) * mask[b * L_ + t] : 0.f;
    sh[t] = am; __syncthreads();
    for (int o = 256; o > 0; o >>= 1) { if (t < o) sh[t] += sh[t + o]; __syncthreads(); }
    float sum2 = sh[0];
    if (t < L_) {
        float a = am / (sum2 + 1e-10f);
        out[OFF_ATTN + b * L_ + t] = a;
        out[OFF_COV + b * L_ + t]  = cov_in[b * L_ + t] + a;
    }
}

__global__ void sent_softmax_k(const float* __restrict__ mask) {
    int b = blockIdx.x, t = threadIdx.x;
    int idx = b * S_ + t;
    float s = -1e30f;
    if (t < S_) {
        s = g_scratch[O_PARTS + idx] + g_scratch[O_PARTS + B_ * S_ + idx]
          + g_scratch[O_PARTS + 2 * B_ * S_ + idx] + g_scratch[O_PARTS + 3 * B_ * S_ + idx];
    }
    float mx = s;
#pragma unroll
    for (int o = 16; o > 0; o >>= 1) mx = fmaxf(mx, __shfl_xor_sync(0xffffffffu, mx, o));
    float e = (t < S_) ? expf(s - mx) : 0.f;
    float sum = e;
#pragma unroll
    for (int o = 16; o > 0; o >>= 1) sum += __shfl_xor_sync(0xffffffffu, sum, o);
    float am = (t < S_) ? (e / sum) * mask[b * S_ + t] : 0.f;
    float sum2 = am;
#pragma unroll
    for (int o = 16; o > 0; o >>= 1) sum2 += __shfl_xor_sync(0xffffffffu, sum2, o);
    if (t < S_) g_scratch[O_ATTNS + b * S_ + t] = am / (sum2 + 1e-10f);
}

__global__ void word_ctx_k(const float* __restrict__ mem, float* __restrict__ out) {
    __shared__ float sa[L_];
    int b = blockIdx.x, t = threadIdx.x;
    if (t < L_) sa[t] = out[OFF_ATTN + b * L_ + t];
    __syncthreads();
    float acc = 0.f;
    const float* mb = mem + (size_t)b * L_ * M_ + t;
#pragma unroll 4
    for (int l = 0; l < L_; l++) acc += sa[l] * mb[(size_t)l * M_];
    out[OFF_WCTX + b * M_ + t] = acc;
    g_scratch[O_CAT + b * 3 * H_ + t] = acc;
}

__global__ void sent_ctx_k(const float* __restrict__ mem) {
    __shared__ float sa[S_];
    int b = blockIdx.x, t = threadIdx.x;
    if (t < S_) sa[t] = g_scratch[O_ATTNS + b * S_ + t];
    __syncthreads();
    float acc = 0.f;
    const float* mb = mem + (size_t)b * S_ * M_ + t;
#pragma unroll 5
    for (int l = 0; l < S_; l++) acc += sa[l] * mb[(size_t)l * M_];
    g_scratch[O_CAT + b * 3 * H_ + H_ + t] = acc;
}

__global__ void pgen_k(const float* __restrict__ pw, const float* __restrict__ pb,
                       float* __restrict__ out) {
    __shared__ float sh[256];
    int b = blockIdx.x, t = threadIdx.x;
    float s = 0.f;
    for (int i = t; i < EMB_ + 3 * H_; i += 256) {
        float x = (i < 3 * H_) ? g_scratch[O_CAT + b * 3 * H_ + i]
                               : g_scratch[O_YEMB + b * EMB_ + (i - 3 * H_)];
        s += pw[i] * x;
    }
    sh[t] = s; __syncthreads();
    for (int o = 128; o > 0; o >>= 1) { if (t < o) sh[t] += sh[t + o]; __syncthreads(); }
    if (t == 0) {
        float p = 1.f / (1.f + expf(-(sh[0] + pb[0])));
        g_scratch[O_PGEN + b] = p;
        out[OFF_PGEN + b] = p;
    }
}

__global__ void vocab_stats_k() {
    __shared__ float sh[1024];
    int b = blockIdx.x, t = threadIdx.x;
    const float* lg = g_scratch + O_LOGITS + (size_t)b * V_;
    float m = -1e30f;
    for (int v = t; v < V_; v += 1024) m = fmaxf(m, lg[v]);
    sh[t] = m; __syncthreads();
    for (int o = 512; o > 0; o >>= 1) { if (t < o) sh[t] = fmaxf(sh[t], sh[t + o]); __syncthreads(); }
    float mx = sh[0]; __syncthreads();
    float s = 0.f;
    for (int v = t; v < V_; v += 1024) s += expf(lg[v] - mx);
    sh[t] = s; __syncthreads();
    for (int o = 512; o > 0; o >>= 1) { if (t < o) sh[t] += sh[t + o]; __syncthreads(); }
    if (t == 0) { g_scratch[O_VMAX + b] = mx; g_scratch[O_VSUM + b] = sh[0]; }
}

__global__ void assemble_k(float* __restrict__ out) {
    int b = blockIdx.y;
    int v = blockIdx.x * 1024 + threadIdx.x;
    if (v >= VX_) return;
    float r;
    if (v < V_) {
        float p = g_scratch[O_PGEN + b];
        r = p * expf(g_scratch[O_LOGITS + (size_t)b * V_ + v] - g_scratch[O_VMAX + b])
              / g_scratch[O_VSUM + b];
    } else {
        r = 0.f;
    }
    out[(size_t)b * VX_ + v] = r;
}

__global__ void scatter_k(const int* __restrict__ src_oov, float* __restrict__ out) {
    int idx = blockIdx.x * 256 + threadIdx.x;
    if (idx >= B_ * L_) return;
    int b = idx / L_;
    float val = (1.f - g_scratch[O_PGEN + b]) * out[OFF_ATTN + idx];
    atomicAdd(&out[(size_t)b * VX_ + src_oov[idx]], val);
}

// =====================================================================
extern "C" void kernel_launch(void* const* d_in, const int* in_sizes, int n_in,
                              void* d_out, int out_size) {
    const float* h_in      = (const float*)d_in[0];
    const float* wmem      = (const float*)d_in[1];
    const float* smemb     = (const float*)d_in[2];
    const float* wmask     = (const float*)d_in[3];
    const float* smask     = (const float*)d_in[4];
    const float* coverage  = (const float*)d_in[5];
    const float* emb       = (const float*)d_in[6];
    const float* gru_w_ih  = (const float*)d_in[7];
    const float* gru_w_hh  = (const float*)d_in[8];
    const float* gru_b_ih  = (const float*)d_in[9];
    const float* gru_b_hh  = (const float*)d_in[10];
    const float* w_mem_proj= (const float*)d_in[11];
    const float* w_dec_w   = (const float*)d_in[12];
    const float* w_dec_b   = (const float*)d_in[13];
    const float* w_v       = (const float*)d_in[14];
    const float* w_covp    = (const float*)d_in[15];
    const float* s_mem_proj= (const float*)d_in[16];
    const float* s_dec_w   = (const float*)d_in[17];
    const float* s_dec_b   = (const float*)d_in[18];
    const float* s_v       = (const float*)d_in[19];
    const float* pgen_w    = (const float*)d_in[20];
    const float* pgen_b    = (const float*)d_in[21];
    const float* vd1_w     = (const float*)d_in[22];
    const float* vd1_b     = (const float*)d_in[23];
    const float* vd2_w     = (const float*)d_in[24];
    const float* vd2_b     = (const float*)d_in[25];
    const int*   y         = (const int*)d_in[26];
    const int*   src_oov   = (const int*)d_in[27];
    float* out = (float*)d_out;

    float* sp = nullptr;
    cudaGetSymbolAddress((void**)&sp, g_scratch);

    static bool attr_done = false;
    if (!attr_done) {
        cudaFuncSetAttribute(feat_score_mma, cudaFuncAttributeMaxDynamicSharedMemorySize, GEMM_SMEM);
        cudaFuncSetAttribute(vd2_mma,        cudaFuncAttributeMaxDynamicSharedMemorySize, GEMM_SMEM);
        attr_done = true;
    }

    // 1. embedding gather
    embed_k<<<B_, EMB_>>>(y, emb);
    // 2/3. GRU input & hidden GEMMs
    sgemm_tn<<<dim3(12, 1), 256>>>(sp + O_YEMB, gru_w_ih, gru_b_ih, sp + O_GI, B_, 3 * H_, EMB_);
    sgemm_tn<<<dim3(12, 1), 256>>>(h_in,        gru_w_hh, gru_b_hh, sp + O_GH, B_, 3 * H_, H_);
    // 4. GRU gates
    gru_gate_k<<<(B_ * H_) / 256, 256>>>(h_in, out);
    // 5/6. decoder projections
    sgemm_tn<<<dim3(4, 1), 256>>>(sp + O_HLAST, w_dec_w, w_dec_b, sp + O_DECW, B_, H_, H_);
    sgemm_tn<<<dim3(4, 1), 256>>>(sp + O_HLAST, s_dec_w, s_dec_b, sp + O_DECS, B_, H_, H_);
    // 7/8. HMMA fused feature GEMM + score epilogue (feat never materialized)
    feat_score_mma<<<dim3(4, (B_ * L_) / 128), 256, GEMM_SMEM>>>(
        wmem, w_mem_proj, sp + O_DECW, coverage, w_covp, w_v, sp + O_PARTW, B_ * L_, L_);
    feat_score_mma<<<dim3(4, (B_ * S_) / 128), 256, GEMM_SMEM>>>(
        smemb, s_mem_proj, sp + O_DECS, nullptr, nullptr, s_v, sp + O_PARTS, B_ * S_, S_);
    // 9/10. masked softmaxes (sum 4 partials inside)
    word_softmax_k<<<B_, 512>>>(wmask, coverage, out);
    sent_softmax_k<<<B_, 32>>>(smask);
    // 11/12. contexts
    word_ctx_k<<<B_, 512>>>(wmem, out);
    sent_ctx_k<<<B_, 512>>>(smemb);
    // 13. hid
    sgemm_tn<<<dim3(4, 1), 256>>>(sp + O_CAT, vd1_w, vd1_b, sp + O_HID, B_, H_, 3 * H_);
    // 14. vocab logits on tensor cores
    vd2_mma<<<(V_ + 127) / 128, 256, GEMM_SMEM>>>(vd2_w, sp + O_HID, vd2_b, sp + O_LOGITS);
    // 15. vocab softmax stats
    vocab_stats_k<<<B_, 1024>>>();
    // 16. p_gen
    pgen_k<<<B_, 256>>>(pgen_w, pgen_b, out);
    // 17. final_dist base
    assemble_k<<<dim3((VX_ + 1023) / 1024, B_), 1024>>>(out);
    // 18. scatter-add copy distribution
    scatter_k<<<(B_ * L_ + 255) / 256, 256>>>(src_oov, out);
}

// round 5
// speedup vs baseline: 1.5979x; 1.1245x over previous
#include <cuda_runtime.h>
#include <cuda_bf16.h>
#include <math.h>
#include <stdint.h>

// Problem dims
#define B_   128
#define L_   400
#define S_   30
#define V_   50000
#define EMB_ 128
#define H_   512
#define M_   512
#define OOV_ 30
#define VX_  (V_ + OOV_)   // 50030

// ---------------- output layout (floats), reference return-tuple order ----------------
#define OFF_FINAL 0
#define OFF_H     (B_*VX_)
#define OFF_WCTX  (OFF_H + B_*H_)
#define OFF_ATTN  (OFF_WCTX + B_*M_)
#define OFF_PGEN  (OFF_ATTN + B_*L_)
#define OFF_COV   (OFF_PGEN + B_)

// ---------------- fp32 scratch layout ----------------
#define O_YEMB    0
#define O_GI      (O_YEMB + B_*EMB_)
#define O_GH      (O_GI + B_*3*H_)
#define O_HLAST   (O_GH + B_*3*H_)
#define O_DECW    (O_HLAST + B_*H_)
#define O_DECS    (O_DECW + B_*H_)
#define O_PARTW   (O_DECS + B_*H_)            // 4*B*L score partials
#define O_PARTS   (O_PARTW + 4*B_*L_)         // 4*B*S
#define O_ATTNS   (O_PARTS + 4*B_*S_)
#define O_CAT     (O_ATTNS + B_*S_)
#define O_HID     (O_CAT + B_*3*H_)
#define O_LOGITS  (O_HID + B_*H_)             // B*V
#define O_VMAX    (O_LOGITS + (size_t)B_*V_)
#define O_VSUM    (O_VMAX + B_)
#define O_PGEN    (O_VSUM + B_)
#define SCRATCH_FLOATS (O_PGEN + B_)

__device__ __align__(256) float g_scratch[SCRATCH_FLOATS];

// ---------------- bf16 hi/lo scratch (element offsets) ----------------
#define BF_WQH  0ull                      // wmem hi     26,214,400
#define BF_WQL  (BF_WQH + 26214400ull)
#define BF_SBH  (BF_WQL + 26214400ull)    // sent bank    1,966,080
#define BF_SBL  (BF_SBH + 1966080ull)
#define BF_WPH  (BF_SBL + 1966080ull)     // w proj         262,144
#define BF_WPL  (BF_WPH + 262144ull)
#define BF_SPH  (BF_WPL + 262144ull)
#define BF_SPL  (BF_SPH + 262144ull)
#define BF_VWH  (BF_SPL + 262144ull)      // vd2_w       25,600,000
#define BF_VWL  (BF_VWH + 25600000ull)
#define BF_HIH  (BF_VWL + 25600000ull)    // hid             65,536
#define BF_HIL  (BF_HIH + 65536ull)
#define BF_TOTAL (BF_HIL + 65536ull)

__device__ __align__(256) __nv_bfloat16 g_bf[BF_TOTAL];

// ===================== HMMA / cp.async helpers =====================
__device__ __forceinline__ uint32_t smem_u32(const void* p) {
    uint32_t a;
    asm("{ .reg .u64 t; cvta.to.shared.u64 t, %1; cvt.u32.u64 %0, t; }" : "=r"(a) : "l"(p));
    return a;
}
__device__ __forceinline__ void ldm4(uint32_t* r, uint32_t addr) {
    asm volatile("ldmatrix.sync.aligned.m8n8.x4.shared.b16 {%0,%1,%2,%3}, [%4];"
                 : "=r"(r[0]), "=r"(r[1]), "=r"(r[2]), "=r"(r[3]) : "r"(addr));
}
__device__ __forceinline__ void mma16816(float* c, const uint32_t* a, const uint32_t* b) {
    asm volatile("mma.sync.aligned.m16n8k16.row.col.f32.bf16.bf16.f32 "
                 "{%0,%1,%2,%3}, {%4,%5,%6,%7}, {%8,%9}, {%0,%1,%2,%3};"
                 : "+f"(c[0]), "+f"(c[1]), "+f"(c[2]), "+f"(c[3])
                 : "r"(a[0]), "r"(a[1]), "r"(a[2]), "r"(a[3]), "r"(b[0]), "r"(b[1]));
}
#define CP16(dst, src) \
    asm volatile("cp.async.cg.shared.global [%0], [%1], 16;" :: "r"(dst), "l"(src))
#define CP_COMMIT() asm volatile("cp.async.commit_group;" ::: "memory")
#define CP_WAIT(n)  asm volatile("cp.async.wait_group %0;" :: "n"(n) : "memory")

// smem tile layout: padded rows of 72 bf16 (144 B), 4 tiles per stage, 2 stages
#define RB   144
#define TILE 18432          // 128 * 144
#define A_HI 0
#define A_LO 18432
#define B_HI 36864
#define B_LO 55296
#define ST   73728          // stage stride
#define PIPE_SMEM (2*ST)    // 147456

// issue one stage: A rows [a_row0, +128), B rows [b_row0, +128), k chunk ch (64 cols)
__device__ __forceinline__ void issue_stage(
    uint32_t stg, const __nv_bfloat16* Ah, const __nv_bfloat16* Al, size_t a_row0,
    const __nv_bfloat16* Bh, const __nv_bfloat16* Bl, size_t b_row0, int ch, int tid) {
    for (int i = tid; i < 1024; i += 256) {
        int r = i >> 3, c16 = i & 7;
        uint32_t dst = stg + (uint32_t)(r * RB + c16 * 16);
        size_t sa = (a_row0 + (size_t)r) * 512 + ch * 64 + c16 * 8;
        size_t sbo = (b_row0 + (size_t)r) * 512 + ch * 64 + c16 * 8;
        CP16(dst + A_HI, Ah + sa);
        CP16(dst + A_LO, Al + sa);
        CP16(dst + B_HI, Bh + sbo);
        CP16(dst + B_LO, Bl + sbo);
    }
}

// =====================================================================
// fp32 -> bf16 hi/lo split converter (per float4)
// =====================================================================
__global__ void cvt_k(const float* __restrict__ src, __nv_bfloat16* __restrict__ hi,
                      __nv_bfloat16* __restrict__ lo, int n4) {
    int i = blockIdx.x * 256 + threadIdx.x;
    if (i >= n4) return;
    float4 x = reinterpret_cast<const float4*>(src)[i];
    __nv_bfloat16 h0 = __float2bfloat16(x.x), h1 = __float2bfloat16(x.y);
    __nv_bfloat16 h2 = __float2bfloat16(x.z), h3 = __float2bfloat16(x.w);
    __nv_bfloat16 l0 = __float2bfloat16(x.x - __bfloat162float(h0));
    __nv_bfloat16 l1 = __float2bfloat16(x.y - __bfloat162float(h1));
    __nv_bfloat16 l2 = __float2bfloat16(x.z - __bfloat162float(h2));
    __nv_bfloat16 l3 = __float2bfloat16(x.w - __bfloat162float(h3));
    uint2 hv, lv;
    hv.x = (uint32_t)__bfloat16_as_ushort(h0) | ((uint32_t)__bfloat16_as_ushort(h1) << 16);
    hv.y = (uint32_t)__bfloat16_as_ushort(h2) | ((uint32_t)__bfloat16_as_ushort(h3) << 16);
    lv.x = (uint32_t)__bfloat16_as_ushort(l0) | ((uint32_t)__bfloat16_as_ushort(l1) << 16);
    lv.y = (uint32_t)__bfloat16_as_ushort(l2) | ((uint32_t)__bfloat16_as_ushort(l3) << 16);
    reinterpret_cast<uint2*>(hi)[i] = hv;
    reinterpret_cast<uint2*>(lo)[i] = lv;
}

// =====================================================================
// Pipelined HMMA feature-GEMM + attention-score epilogue (bf16 hi/lo inputs).
// partial[nb*total+row] = sum over 128-col slice of v[d]*tanh(feat+dec[b,d]+cov*covproj[d])
// grid = (4, total/128); block = 256 (8 warps: wm 0-3 x wn 0-1, warp tile 32x64)
// =====================================================================
__global__ __launch_bounds__(256)
void feat_score_mma(const __nv_bfloat16* __restrict__ Ah, const __nv_bfloat16* __restrict__ Al,
                    const __nv_bfloat16* __restrict__ Bh, const __nv_bfloat16* __restrict__ Bl,
                    const float* __restrict__ dec, const float* __restrict__ cov,
                    const float* __restrict__ covproj, const float* __restrict__ v,
                    float* __restrict__ partial, int total, int Lrow) {
    extern __shared__ char smem[];
    __shared__ float sv[128], scp[128], spart[2][128];
    const uint32_t sb = smem_u32(smem);
    const int tid = threadIdx.x;
    const int lane = tid & 31, wid = tid >> 5;
    const int wm = wid & 3, wn = wid >> 2;
    const int bm = blockIdx.y * 128;
    const int nb = blockIdx.x;

    if (tid < 128) {
        sv[tid]  = v[nb * 128 + tid];
        scp[tid] = covproj ? covproj[nb * 128 + tid] : 0.f;
    }

    float acc[2][8][4];
#pragma unroll
    for (int mt = 0; mt < 2; mt++)
#pragma unroll
        for (int nt = 0; nt < 8; nt++)
#pragma unroll
            for (int e = 0; e < 4; e++) acc[mt][nt][e] = 0.f;

    const uint32_t a_row = (uint32_t)(wm * 32 + (lane & 15));
    const uint32_t a_koff = (uint32_t)((lane >> 4) * 16);
    const uint32_t b_row0 = (uint32_t)(wn * 64 + ((lane >> 4) & 1) * 8 + (lane & 7));
    const uint32_t b_koff = (uint32_t)(((lane >> 3) & 1) * 16);

    issue_stage(sb, Ah, Al, (size_t)bm, Bh, Bl, (size_t)nb * 128, 0, tid);
    CP_COMMIT();

    for (int ch = 0; ch < 8; ch++) {
        if (ch < 7) {
            issue_stage(sb + ((ch + 1) & 1) * ST, Ah, Al, (size_t)bm,
                        Bh, Bl, (size_t)nb * 128, ch + 1, tid);
            CP_COMMIT();
            CP_WAIT(1);
        } else {
            CP_WAIT(0);
        }
        __syncthreads();
        const uint32_t stg = sb + (ch & 1) * ST;
#pragma unroll
        for (int ks = 0; ks < 4; ks++) {
            uint32_t ah[2][4], al[2][4], bh[4][4], bl[4][4];
#pragma unroll
            for (int mt = 0; mt < 2; mt++) {
                uint32_t off = (a_row + mt * 16) * RB + ks * 32 + a_koff;
                ldm4(ah[mt], stg + A_HI + off);
                ldm4(al[mt], stg + A_LO + off);
            }
#pragma unroll
            for (int ng = 0; ng < 4; ng++) {
                uint32_t off = (b_row0 + ng * 16) * RB + ks * 32 + b_koff;
                ldm4(bh[ng], stg + B_HI + off);
                ldm4(bl[ng], stg + B_LO + off);
            }
#pragma unroll
            for (int mt = 0; mt < 2; mt++)
#pragma unroll
                for (int ng = 0; ng < 4; ng++) {
                    mma16816(acc[mt][2 * ng],     ah[mt], &bh[ng][0]);
                    mma16816(acc[mt][2 * ng + 1], ah[mt], &bh[ng][2]);
                    mma16816(acc[mt][2 * ng],     ah[mt], &bl[ng][0]);
                    mma16816(acc[mt][2 * ng + 1], ah[mt], &bl[ng][2]);
                    mma16816(acc[mt][2 * ng],     al[mt], &bh[ng][0]);
                    mma16816(acc[mt][2 * ng + 1], al[mt], &bh[ng][2]);
                }
        }
        __syncthreads();
    }

    // epilogue: per-row partial score over this 128-col slice
    const int g = lane >> 2, t4 = lane & 3;
#pragma unroll
    for (int mt = 0; mt < 2; mt++)
#pragma unroll
        for (int h = 0; h < 2; h++) {
            int rl = wm * 32 + mt * 16 + h * 8 + g;
            int row = bm + rl;
            int b = row / Lrow;
            float c = cov ? cov[row] : 0.f;
            const float* db = dec + (size_t)b * 512 + nb * 128;
            float s = 0.f;
#pragma unroll
            for (int nt = 0; nt < 8; nt++)
#pragma unroll
                for (int e = 0; e < 2; e++) {
                    int cl = wn * 64 + nt * 8 + t4 * 2 + e;
                    float x = acc[mt][nt][h * 2 + e] + db[cl] + c * scp[cl];
                    s += sv[cl] * tanhf(x);
                }
            s += __shfl_xor_sync(0xffffffffu, s, 1);
            s += __shfl_xor_sync(0xffffffffu, s, 2);
            if (t4 == 0) spart[wn][rl] = s;
        }
    __syncthreads();
    if (tid < 128)
        partial[(size_t)nb * total + bm + tid] = spart[0][tid] + spart[1][tid];
}

// =====================================================================
// Pipelined HMMA vocab-logits GEMM (bf16 hi/lo inputs).
// logits[b, v] = hid[b,:] . W[v,:] + bias[v]; grid.x over W row blocks.
// =====================================================================
__global__ __launch_bounds__(256)
void vd2_mma(const __nv_bfloat16* __restrict__ Wh, const __nv_bfloat16* __restrict__ Wl,
             const __nv_bfloat16* __restrict__ Hh, const __nv_bfloat16* __restrict__ Hl,
             const float* __restrict__ bias, float* __restrict__ logits) {
    extern __shared__ char smem[];
    const uint32_t sb = smem_u32(smem);
    const int tid = threadIdx.x;
    const int lane = tid & 31, wid = tid >> 5;
    const int wm = wid & 3, wn = wid >> 2;
    const int bm = blockIdx.x * 128;

    float acc[2][8][4];
#pragma unroll
    for (int mt = 0; mt < 2; mt++)
#pragma unroll
        for (int nt = 0; nt < 8; nt++)
#pragma unroll
            for (int e = 0; e < 4; e++) acc[mt][nt][e] = 0.f;

    const uint32_t a_row = (uint32_t)(wm * 32 + (lane & 15));
    const uint32_t a_koff = (uint32_t)((lane >> 4) * 16);
    const uint32_t b_row0 = (uint32_t)(wn * 64 + ((lane >> 4) & 1) * 8 + (lane & 7));
    const uint32_t b_koff = (uint32_t)(((lane >> 3) & 1) * 16);

    // issue with W-row clamp (tail block)
    auto issue_v = [&](uint32_t stg, int ch) {
        for (int i = tid; i < 1024; i += 256) {
            int r = i >> 3, c16 = i & 7;
            int rg = bm + r; if (rg >= V_) rg = V_ - 1;
            uint32_t dst = stg + (uint32_t)(r * RB + c16 * 16);
            size_t sa = (size_t)rg * 512 + ch * 64 + c16 * 8;
            size_t sbo = (size_t)r * 512 + ch * 64 + c16 * 8;
            CP16(dst + A_HI, Wh + sa);
            CP16(dst + A_LO, Wl + sa);
            CP16(dst + B_HI, Hh + sbo);
            CP16(dst + B_LO, Hl + sbo);
        }
    };

    issue_v(sb, 0);
    CP_COMMIT();
    for (int ch = 0; ch < 8; ch++) {
        if (ch < 7) { issue_v(sb + ((ch + 1) & 1) * ST, ch + 1); CP_COMMIT(); CP_WAIT(1); }
        else        { CP_WAIT(0); }
        __syncthreads();
        const uint32_t stg = sb + (ch & 1) * ST;
#pragma unroll
        for (int ks = 0; ks < 4; ks++) {
            uint32_t ah[2][4], al[2][4], bh[4][4], bl[4][4];
#pragma unroll
            for (int mt = 0; mt < 2; mt++) {
                uint32_t off = (a_row + mt * 16) * RB + ks * 32 + a_koff;
                ldm4(ah[mt], stg + A_HI + off);
                ldm4(al[mt], stg + A_LO + off);
            }
#pragma unroll
            for (int ng = 0; ng < 4; ng++) {
                uint32_t off = (b_row0 + ng * 16) * RB + ks * 32 + b_koff;
                ldm4(bh[ng], stg + B_HI + off);
                ldm4(bl[ng], stg + B_LO + off);
            }
#pragma unroll
            for (int mt = 0; mt < 2; mt++)
#pragma unroll
                for (int ng = 0; ng < 4; ng++) {
                    mma16816(acc[mt][2 * ng],     ah[mt], &bh[ng][0]);
                    mma16816(acc[mt][2 * ng + 1], ah[mt], &bh[ng][2]);
                    mma16816(acc[mt][2 * ng],     ah[mt], &bl[ng][0]);
                    mma16816(acc[mt][2 * ng + 1], ah[mt], &bl[ng][2]);
                    mma16816(acc[mt][2 * ng],     al[mt], &bh[ng][0]);
                    mma16816(acc[mt][2 * ng + 1], al[mt], &bh[ng][2]);
                }
        }
        __syncthreads();
    }

    // epilogue: transpose via padded smem (pad 133 -> conflict-free)
    __syncthreads();
    float* tr = (float*)smem;   // 128*133*4 = 68096 <= PIPE_SMEM
    const int g = lane >> 2, t4 = lane & 3;
#pragma unroll
    for (int mt = 0; mt < 2; mt++)
#pragma unroll
        for (int h = 0; h < 2; h++) {
            int vl = wm * 32 + mt * 16 + h * 8 + g;
            int vg = bm + vl; int vc = vg < V_ ? vg : V_ - 1;
            float bia = bias[vc];
#pragma unroll
            for (int nt = 0; nt < 8; nt++)
#pragma unroll
                for (int e = 0; e < 2; e++) {
                    int cb = wn * 64 + nt * 8 + t4 * 2 + e;
                    tr[vl * 133 + cb] = acc[mt][nt][h * 2 + e] + bia;
                }
        }
    __syncthreads();
    for (int i = tid; i < 16384; i += 256) {
        int b = i >> 7, vl = i & 127;
        int vg = bm + vl;
        if (vg < V_) logits[(size_t)b * V_ + vg] = tr[vl * 133 + b];
    }
}

// =====================================================================
// SIMT fp32 GEMM for the small layers: C[M,N] = A[M,K]*B[N,K]^T (+bias)
// =====================================================================
__global__ __launch_bounds__(256)
void sgemm_tn(const float* __restrict__ A, const float* __restrict__ Bm,
              const float* __restrict__ bias, float* __restrict__ C,
              int M, int N, int K) {
    __shared__ float As[8][128];
    __shared__ float Bs[8][128];
    const int bm = blockIdx.y * 128;
    const int bn = blockIdx.x * 128;
    const int tid = threadIdx.x;
    const int tx = tid & 15, ty = tid >> 4;
    const int lrow = tid >> 1, lk4 = (tid & 1) * 4;

    float acc[8][8];
#pragma unroll
    for (int i = 0; i < 8; i++)
#pragma unroll
        for (int j = 0; j < 8; j++) acc[i][j] = 0.f;

    const float* Aptr = A + (size_t)(bm + lrow) * K + lk4;
    const bool bvalid = (bn + lrow) < N;
    const float* Bptr = Bm + (size_t)(bvalid ? (bn + lrow) : 0) * K + lk4;

    for (int k0 = 0; k0 < K; k0 += 8) {
        float4 a4 = *reinterpret_cast<const float4*>(Aptr + k0);
        float4 b4 = bvalid ? *reinterpret_cast<const float4*>(Bptr + k0)
                           : make_float4(0.f, 0.f, 0.f, 0.f);
        As[lk4 + 0][lrow] = a4.x; As[lk4 + 1][lrow] = a4.y;
        As[lk4 + 2][lrow] = a4.z; As[lk4 + 3][lrow] = a4.w;
        Bs[lk4 + 0][lrow] = b4.x; Bs[lk4 + 1][lrow] = b4.y;
        Bs[lk4 + 2][lrow] = b4.z; Bs[lk4 + 3][lrow] = b4.w;
        __syncthreads();
#pragma unroll
        for (int kk = 0; kk < 8; kk++) {
            float af[8], bf[8];
#pragma unroll
            for (int i = 0; i < 8; i++) af[i] = As[kk][ty * 8 + i];
#pragma unroll
            for (int j = 0; j < 8; j++) bf[j] = Bs[kk][tx * 8 + j];
#pragma unroll
            for (int i = 0; i < 8; i++)
#pragma unroll
                for (int j = 0; j < 8; j++) acc[i][j] += af[i] * bf[j];
        }
        __syncthreads();
    }
#pragma unroll
    for (int i = 0; i < 8; i++) {
        int row = bm + ty * 8 + i;
#pragma unroll
        for (int j = 0; j < 8; j++) {
            int col = bn + tx * 8 + j;
            if (col < N) C[(size_t)row * N + col] = acc[i][j] + (bias ? bias[col] : 0.f);
        }
    }
}

// =====================================================================
// Small kernels
// =====================================================================
__global__ void embed_k(const int* __restrict__ y, const float* __restrict__ emb) {
    int b = blockIdx.x, t = threadIdx.x;
    g_scratch[O_YEMB + b * EMB_ + t] = emb[(size_t)y[b] * EMB_ + t];
}

__global__ void gru_gate_k(const float* __restrict__ h_prev, float* __restrict__ out) {
    int idx = blockIdx.x * blockDim.x + threadIdx.x;
    int b = idx / H_, d = idx % H_;
    const float* gi = g_scratch + O_GI + b * 3 * H_;
    const float* gh = g_scratch + O_GH + b * 3 * H_;
    float r = 1.f / (1.f + expf(-(gi[d] + gh[d])));
    float z = 1.f / (1.f + expf(-(gi[H_ + d] + gh[H_ + d])));
    float n = tanhf(gi[2 * H_ + d] + r * gh[2 * H_ + d]);
    float hp = h_prev[b * H_ + d];
    float hl = (1.f - z) * n + z * hp;
    g_scratch[O_HLAST + b * H_ + d] = hl;
    g_scratch[O_CAT + b * 3 * H_ + 2 * H_ + d] = hl;
    out[OFF_H + b * H_ + d] = hl;
}

__global__ void word_softmax_k(const float* __restrict__ mask,
                               const float* __restrict__ cov_in,
                               float* __restrict__ out) {
    __shared__ float sh[512];
    int b = blockIdx.x, t = threadIdx.x;
    int idx = b * L_ + t;
    float s = -1e30f;
    if (t < L_) {
        s = g_scratch[O_PARTW + idx] + g_scratch[O_PARTW + B_ * L_ + idx]
          + g_scratch[O_PARTW + 2 * B_ * L_ + idx] + g_scratch[O_PARTW + 3 * B_ * L_ + idx];
    }
    sh[t] = s; __syncthreads();
    for (int o = 256; o > 0; o >>= 1) { if (t < o) sh[t] = fmaxf(sh[t], sh[t + o]); __syncthreads(); }
    float mx = sh[0]; __syncthreads();
    float e = (t < L_) ? expf(s - mx) : 0.f;
    sh[t] = e; __syncthreads();
    for (int o = 256; o > 0; o >>= 1) { if (t < o) sh[t] += sh[t + o]; __syncthreads(); }
    float sum = sh[0]; __syncthreads();
    float am = (t < L_) ? (e / sum) * mask[b * L_ + t] : 0.f;
    sh[t] = am; __syncthreads();
    for (int o = 256; o > 0; o >>= 1) { if (t < o) sh[t] += sh[t + o]; __syncthreads(); }
    float sum2 = sh[0];
    if (t < L_) {
        float a = am / (sum2 + 1e-10f);
        out[OFF_ATTN + b * L_ + t] = a;
        out[OFF_COV + b * L_ + t]  = cov_in[b * L_ + t] + a;
    }
}

__global__ void sent_softmax_k(const float* __restrict__ mask) {
    int b = blockIdx.x, t = threadIdx.x;
    int idx = b * S_ + t;
    float s = -1e30f;
    if (t < S_) {
        s = g_scratch[O_PARTS + idx] + g_scratch[O_PARTS + B_ * S_ + idx]
          + g_scratch[O_PARTS + 2 * B_ * S_ + idx] + g_scratch[O_PARTS + 3 * B_ * S_ + idx];
    }
    float mx = s;
#pragma unroll
    for (int o = 16; o > 0; o >>= 1) mx = fmaxf(mx, __shfl_xor_sync(0xffffffffu, mx, o));
    float e = (t < S_) ? expf(s - mx) : 0.f;
    float sum = e;
#pragma unroll
    for (int o = 16; o > 0; o >>= 1) sum += __shfl_xor_sync(0xffffffffu, sum, o);
    float am = (t < S_) ? (e / sum) * mask[b * S_ + t] : 0.f;
    float sum2 = am;
#pragma unroll
    for (int o = 16; o > 0; o >>= 1) sum2 += __shfl_xor_sync(0xffffffffu, sum2, o);
    if (t < S_) g_scratch[O_ATTNS + b * S_ + t] = am / (sum2 + 1e-10f);
}

__global__ void word_ctx_k(const float* __restrict__ mem, float* __restrict__ out) {
    __shared__ float sa[L_];
    int b = blockIdx.x, t = threadIdx.x;
    if (t < L_) sa[t] = out[OFF_ATTN + b * L_ + t];
    __syncthreads();
    float acc = 0.f;
    const float* mb = mem + (size_t)b * L_ * M_ + t;
#pragma unroll 4
    for (int l = 0; l < L_; l++) acc += sa[l] * mb[(size_t)l * M_];
    out[OFF_WCTX + b * M_ + t] = acc;
    g_scratch[O_CAT + b * 3 * H_ + t] = acc;
}

__global__ void sent_ctx_k(const float* __restrict__ mem) {
    __shared__ float sa[S_];
    int b = blockIdx.x, t = threadIdx.x;
    if (t < S_) sa[t] = g_scratch[O_ATTNS + b * S_ + t];
    __syncthreads();
    float acc = 0.f;
    const float* mb = mem + (size_t)b * S_ * M_ + t;
#pragma unroll 5
    for (int l = 0; l < S_; l++) acc += sa[l] * mb[(size_t)l * M_];
    g_scratch[O_CAT + b * 3 * H_ + H_ + t] = acc;
}

__global__ void pgen_k(const float* __restrict__ pw, const float* __restrict__ pb,
                       float* __restrict__ out) {
    __shared__ float sh[256];
    int b = blockIdx.x, t = threadIdx.x;
    float s = 0.f;
    for (int i = t; i < EMB_ + 3 * H_; i += 256) {
        float x = (i < 3 * H_) ? g_scratch[O_CAT + b * 3 * H_ + i]
                               : g_scratch[O_YEMB + b * EMB_ + (i - 3 * H_)];
        s += pw[i] * x;
    }
    sh[t] = s; __syncthreads();
    for (int o = 128; o > 0; o >>= 1) { if (t < o) sh[t] += sh[t + o]; __syncthreads(); }
    if (t == 0) {
        float p = 1.f / (1.f + expf(-(sh[0] + pb[0])));
        g_scratch[O_PGEN + b] = p;
        out[OFF_PGEN + b] = p;
    }
}

__global__ void vocab_stats_k() {
    __shared__ float sh[1024];
    int b = blockIdx.x, t = threadIdx.x;
    const float* lg = g_scratch + O_LOGITS + (size_t)b * V_;
    float m = -1e30f;
    for (int v = t; v < V_; v += 1024) m = fmaxf(m, lg[v]);
    sh[t] = m; __syncthreads();
    for (int o = 512; o > 0; o >>= 1) { if (t < o) sh[t] = fmaxf(sh[t], sh[t + o]); __syncthreads(); }
    float mx = sh[0]; __syncthreads();
    float s = 0.f;
    for (int v = t; v < V_; v += 1024) s += expf(lg[v] - mx);
    sh[t] = s; __syncthreads();
    for (int o = 512; o > 0; o >>= 1) { if (t < o) sh[t] += sh[t + o]; __syncthreads(); }
    if (t == 0) { g_scratch[O_VMAX + b] = mx; g_scratch[O_VSUM + b] = sh[0]; }
}

__global__ void assemble_k(float* __restrict__ out) {
    int b = blockIdx.y;
    int v = blockIdx.x * 1024 + threadIdx.x;
    if (v >= VX_) return;
    float r;
    if (v < V_) {
        float p = g_scratch[O_PGEN + b];
        r = p * expf(g_scratch[O_LOGITS + (size_t)b * V_ + v] - g_scratch[O_VMAX + b])
              / g_scratch[O_VSUM + b];
    } else {
        r = 0.f;
    }
    out[(size_t)b * VX_ + v] = r;
}

__global__ void scatter_k(const int* __restrict__ src_oov, float* __restrict__ out) {
    int idx = blockIdx.x * 256 + threadIdx.x;
    if (idx >= B_ * L_) return;
    int b = idx / L_;
    float val = (1.f - g_scratch[O_PGEN + b]) * out[OFF_ATTN + idx];
    atomicAdd(&out[(size_t)b * VX_ + src_oov[idx]], val);
}

// =====================================================================
extern "C" void kernel_launch(void* const* d_in, const int* in_sizes, int n_in,
                              void* d_out, int out_size) {
    const float* h_in      = (const float*)d_in[0];
    const float* wmem      = (const float*)d_in[1];
    const float* smemb     = (const float*)d_in[2];
    const float* wmask     = (const float*)d_in[3];
    const float* smask     = (const float*)d_in[4];
    const float* coverage  = (const float*)d_in[5];
    const float* emb       = (const float*)d_in[6];
    const float* gru_w_ih  = (const float*)d_in[7];
    const float* gru_w_hh  = (const float*)d_in[8];
    const float* gru_b_ih  = (const float*)d_in[9];
    const float* gru_b_hh  = (const float*)d_in[10];
    const float* w_mem_proj= (const float*)d_in[11];
    const float* w_dec_w   = (const float*)d_in[12];
    const float* w_dec_b   = (const float*)d_in[13];
    const float* w_v       = (const float*)d_in[14];
    const float* w_covp    = (const float*)d_in[15];
    const float* s_mem_proj= (const float*)d_in[16];
    const float* s_dec_w   = (const float*)d_in[17];
    const float* s_dec_b   = (const float*)d_in[18];
    const float* s_v       = (const float*)d_in[19];
    const float* pgen_w    = (const float*)d_in[20];
    const float* pgen_b    = (const float*)d_in[21];
    const float* vd1_w     = (const float*)d_in[22];
    const float* vd1_b     = (const float*)d_in[23];
    const float* vd2_w     = (const float*)d_in[24];
    const float* vd2_b     = (const float*)d_in[25];
    const int*   y         = (const int*)d_in[26];
    const int*   src_oov   = (const int*)d_in[27];
    float* out = (float*)d_out;

    float* sp = nullptr;
    cudaGetSymbolAddress((void**)&sp, g_scratch);
    __nv_bfloat16* bp = nullptr;
    cudaGetSymbolAddress((void**)&bp, g_bf);

    static bool attr_done = false;
    if (!attr_done) {
        cudaFuncSetAttribute(feat_score_mma, cudaFuncAttributeMaxDynamicSharedMemorySize, PIPE_SMEM);
        cudaFuncSetAttribute(vd2_mma,        cudaFuncAttributeMaxDynamicSharedMemorySize, PIPE_SMEM);
        attr_done = true;
    }

    // 0. pre-convert big operands to bf16 hi/lo
    cvt_k<<<(B_*L_*512/4 + 255)/256, 256>>>(wmem,       bp + BF_WQH, bp + BF_WQL, B_*L_*512/4);
    cvt_k<<<(B_*S_*512/4 + 255)/256, 256>>>(smemb,      bp + BF_SBH, bp + BF_SBL, B_*S_*512/4);
    cvt_k<<<(512*512/4   + 255)/256, 256>>>(w_mem_proj, bp + BF_WPH, bp + BF_WPL, 512*512/4);
    cvt_k<<<(512*512/4   + 255)/256, 256>>>(s_mem_proj, bp + BF_SPH, bp + BF_SPL, 512*512/4);
    cvt_k<<<(V_*512/4    + 255)/256, 256>>>(vd2_w,      bp + BF_VWH, bp + BF_VWL, V_*512/4);

    // 1. embedding gather
    embed_k<<<B_, EMB_>>>(y, emb);
    // 2/3. GRU input & hidden GEMMs
    sgemm_tn<<<dim3(12, 1), 256>>>(sp + O_YEMB, gru_w_ih, gru_b_ih, sp + O_GI, B_, 3 * H_, EMB_);
    sgemm_tn<<<dim3(12, 1), 256>>>(h_in,        gru_w_hh, gru_b_hh, sp + O_GH, B_, 3 * H_, H_);
    // 4. GRU gates
    gru_gate_k<<<(B_ * H_) / 256, 256>>>(h_in, out);
    // 5/6. decoder projections
    sgemm_tn<<<dim3(4, 1), 256>>>(sp + O_HLAST, w_dec_w, w_dec_b, sp + O_DECW, B_, H_, H_);
    sgemm_tn<<<dim3(4, 1), 256>>>(sp + O_HLAST, s_dec_w, s_dec_b, sp + O_DECS, B_, H_, H_);
    // 7/8. pipelined HMMA fused feature GEMM + score epilogue
    feat_score_mma<<<dim3(4, (B_ * L_) / 128), 256, PIPE_SMEM>>>(
        bp + BF_WQH, bp + BF_WQL, bp + BF_WPH, bp + BF_WPL,
        sp + O_DECW, coverage, w_covp, w_v, sp + O_PARTW, B_ * L_, L_);
    feat_score_mma<<<dim3(4, (B_ * S_) / 128), 256, PIPE_SMEM>>>(
        bp + BF_SBH, bp + BF_SBL, bp + BF_SPH, bp + BF_SPL,
        sp + O_DECS, nullptr, nullptr, s_v, sp + O_PARTS, B_ * S_, S_);
    // 9/10. masked softmaxes
    word_softmax_k<<<B_, 512>>>(wmask, coverage, out);
    sent_softmax_k<<<B_, 32>>>(smask);
    // 11/12. contexts
    word_ctx_k<<<B_, 512>>>(wmem, out);
    sent_ctx_k<<<B_, 512>>>(smemb);
    // 13. hid + convert
    sgemm_tn<<<dim3(4, 1), 256>>>(sp + O_CAT, vd1_w, vd1_b, sp + O_HID, B_, H_, 3 * H_);
    cvt_k<<<(B_*H_/4 + 255)/256, 256>>>(sp + O_HID, bp + BF_HIH, bp + BF_HIL, B_*H_/4);
    // 14. vocab logits (pipelined HMMA)
    vd2_mma<<<(V_ + 127) / 128, 256, PIPE_SMEM>>>(bp + BF_VWH, bp + BF_VWL,
                                                  bp + BF_HIH, bp + BF_HIL, vd2_b, sp + O_LOGITS);
    // 15. vocab softmax stats
    vocab_stats_k<<<B_, 1024>>>();
    // 16. p_gen
    pgen_k<<<B_, 256>>>(pgen_w, pgen_b, out);
    // 17. final_dist base
    assemble_k<<<dim3((VX_ + 1023) / 1024, B_), 1024>>>(out);
    // 18. scatter-add copy distribution
    scatter_k<<<(B_ * L_ + 255) / 256, 256>>>(src_oov, out);
}

// round 6
// speedup vs baseline: 2.6129x; 1.6352x over previous
#include <cuda_runtime.h>
#include <cuda_bf16.h>
#include <math.h>
#include <stdint.h>

// Problem dims
#define B_   128
#define L_   400
#define S_   30
#define V_   50000
#define EMB_ 128
#define H_   512
#define M_   512
#define OOV_ 30
#define VX_  (V_ + OOV_)   // 50030

// ---------------- output layout (floats), reference return-tuple order ----------------
#define OFF_FINAL 0
#define OFF_H     (B_*VX_)
#define OFF_WCTX  (OFF_H + B_*H_)
#define OFF_ATTN  (OFF_WCTX + B_*M_)
#define OFF_PGEN  (OFF_ATTN + B_*L_)
#define OFF_COV   (OFF_PGEN + B_)

// ---------------- fp32 scratch layout ----------------
#define O_YEMB    0
#define O_GI      (O_YEMB + B_*EMB_)
#define O_GH      (O_GI + B_*3*H_)
#define O_HLAST   (O_GH + B_*3*H_)
#define O_DECW    (O_HLAST + B_*H_)
#define O_DECS    (O_DECW + B_*H_)
#define O_PARTW   (O_DECS + B_*H_)            // 2*B*L score partials
#define O_PARTS   (O_PARTW + 2*B_*L_)         // 2*B*S
#define O_ATTNS   (O_PARTS + 2*B_*S_)
#define O_CAT     (O_ATTNS + B_*S_)
#define O_HID     (O_CAT + B_*3*H_)           // k-half 0
#define O_HID2    (O_HID + B_*H_)             // k-half 1
#define O_LOGITS  (O_HID2 + B_*H_)            // B*V
#define O_VMAX    (O_LOGITS + (size_t)B_*V_)
#define O_VSUM    (O_VMAX + B_)
#define O_PGEN    (O_VSUM + B_)
#define SCRATCH_FLOATS (O_PGEN + B_)

__device__ __align__(256) float g_scratch[SCRATCH_FLOATS];

// ---------------- bf16 hi/lo scratch (element offsets) ----------------
#define BF_WQH  0ull
#define BF_WQL  (BF_WQH + 26214400ull)
#define BF_SBH  (BF_WQL + 26214400ull)
#define BF_SBL  (BF_SBH + 1966080ull)
#define BF_WPH  (BF_SBL + 1966080ull)
#define BF_WPL  (BF_WPH + 262144ull)
#define BF_SPH  (BF_WPL + 262144ull)
#define BF_SPL  (BF_SPH + 262144ull)
#define BF_VWH  (BF_SPL + 262144ull)
#define BF_VWL  (BF_VWH + 25600000ull)
#define BF_HIH  (BF_VWL + 25600000ull)
#define BF_HIL  (BF_HIH + 65536ull)
#define BF_TOTAL (BF_HIL + 65536ull)

__device__ __align__(256) __nv_bfloat16 g_bf[BF_TOTAL];

// ===================== HMMA / cp.async helpers =====================
__device__ __forceinline__ uint32_t smem_u32(const void* p) {
    uint32_t a;
    asm("{ .reg .u64 t; cvta.to.shared.u64 t, %1; cvt.u32.u64 %0, t; }" : "=r"(a) : "l"(p));
    return a;
}
__device__ __forceinline__ void ldm4(uint32_t* r, uint32_t addr) {
    asm volatile("ldmatrix.sync.aligned.m8n8.x4.shared.b16 {%0,%1,%2,%3}, [%4];"
                 : "=r"(r[0]), "=r"(r[1]), "=r"(r[2]), "=r"(r[3]) : "r"(addr));
}
__device__ __forceinline__ void mma16816(float* c, const uint32_t* a, const uint32_t* b) {
    asm volatile("mma.sync.aligned.m16n8k16.row.col.f32.bf16.bf16.f32 "
                 "{%0,%1,%2,%3}, {%4,%5,%6,%7}, {%8,%9}, {%0,%1,%2,%3};"
                 : "+f"(c[0]), "+f"(c[1]), "+f"(c[2]), "+f"(c[3])
                 : "r"(a[0]), "r"(a[1]), "r"(a[2]), "r"(a[3]), "r"(b[0]), "r"(b[1]));
}
#define CP16(dst, src) \
    asm volatile("cp.async.cg.shared.global [%0], [%1], 16;" :: "r"(dst), "l"(src))
#define CP_COMMIT() asm volatile("cp.async.commit_group;" ::: "memory")
#define CP_WAIT(n)  asm volatile("cp.async.wait_group %0;" :: "n"(n) : "memory")

#define RB 144    // padded row bytes (64 bf16 data + pad)

// ---- feat kernel smem (128x256 tile, 512 threads) ----
#define FA_HI 0
#define FA_LO 18432
#define FB_HI 36864
#define FB_LO 73728
#define FST   110592
#define FPIPE (2*FST)       // 221184

// ---- vd2 kernel smem (128x128 tile, 256 threads) ----
#define VA_HI 0
#define VA_LO 18432
#define VB_HI 36864
#define VB_LO 55296
#define VST   73728
#define VPIPE (2*VST)       // 147456

// =====================================================================
// fp32 -> bf16 hi/lo split converter
// =====================================================================
__global__ void cvt_k(const float* __restrict__ src, __nv_bfloat16* __restrict__ hi,
                      __nv_bfloat16* __restrict__ lo, int n4) {
    int i = blockIdx.x * 256 + threadIdx.x;
    if (i >= n4) return;
    float4 x = reinterpret_cast<const float4*>(src)[i];
    __nv_bfloat16 h0 = __float2bfloat16(x.x), h1 = __float2bfloat16(x.y);
    __nv_bfloat16 h2 = __float2bfloat16(x.z), h3 = __float2bfloat16(x.w);
    __nv_bfloat16 l0 = __float2bfloat16(x.x - __bfloat162float(h0));
    __nv_bfloat16 l1 = __float2bfloat16(x.y - __bfloat162float(h1));
    __nv_bfloat16 l2 = __float2bfloat16(x.z - __bfloat162float(h2));
    __nv_bfloat16 l3 = __float2bfloat16(x.w - __bfloat162float(h3));
    uint2 hv, lv;
    hv.x = (uint32_t)__bfloat16_as_ushort(h0) | ((uint32_t)__bfloat16_as_ushort(h1) << 16);
    hv.y = (uint32_t)__bfloat16_as_ushort(h2) | ((uint32_t)__bfloat16_as_ushort(h3) << 16);
    lv.x = (uint32_t)__bfloat16_as_ushort(l0) | ((uint32_t)__bfloat16_as_ushort(l1) << 16);
    lv.y = (uint32_t)__bfloat16_as_ushort(l2) | ((uint32_t)__bfloat16_as_ushort(l3) << 16);
    reinterpret_cast<uint2*>(hi)[i] = hv;
    reinterpret_cast<uint2*>(lo)[i] = lv;
}

// sum two fp32 k-half partials, then bf16 hi/lo split (for hid -> vd2)
__global__ void cvt_hid_sum(const float* __restrict__ p0, const float* __restrict__ p1,
                            __nv_bfloat16* __restrict__ hi, __nv_bfloat16* __restrict__ lo,
                            int n4) {
    int i = blockIdx.x * 256 + threadIdx.x;
    if (i >= n4) return;
    float4 a = reinterpret_cast<const float4*>(p0)[i];
    float4 b = reinterpret_cast<const float4*>(p1)[i];
    float4 x = make_float4(a.x + b.x, a.y + b.y, a.z + b.z, a.w + b.w);
    __nv_bfloat16 h0 = __float2bfloat16(x.x), h1 = __float2bfloat16(x.y);
    __nv_bfloat16 h2 = __float2bfloat16(x.z), h3 = __float2bfloat16(x.w);
    __nv_bfloat16 l0 = __float2bfloat16(x.x - __bfloat162float(h0));
    __nv_bfloat16 l1 = __float2bfloat16(x.y - __bfloat162float(h1));
    __nv_bfloat16 l2 = __float2bfloat16(x.z - __bfloat162float(h2));
    __nv_bfloat16 l3 = __float2bfloat16(x.w - __bfloat162float(h3));
    uint2 hv, lv;
    hv.x = (uint32_t)__bfloat16_as_ushort(h0) | ((uint32_t)__bfloat16_as_ushort(h1) << 16);
    hv.y = (uint32_t)__bfloat16_as_ushort(h2) | ((uint32_t)__bfloat16_as_ushort(h3) << 16);
    lv.x = (uint32_t)__bfloat16_as_ushort(l0) | ((uint32_t)__bfloat16_as_ushort(l1) << 16);
    lv.y = (uint32_t)__bfloat16_as_ushort(l2) | ((uint32_t)__bfloat16_as_ushort(l3) << 16);
    reinterpret_cast<uint2*>(hi)[i] = hv;
    reinterpret_cast<uint2*>(lo)[i] = lv;
}

// =====================================================================
// 64x64-tile SIMT fp32 GEMM core (128 threads): C = A*B^T (+bias)
// =====================================================================
__device__ __forceinline__ void sgemm64_core(
    const float* __restrict__ A, int lda, const float* __restrict__ Bm, int ldb,
    const float* __restrict__ bias, float* __restrict__ C, int ldc,
    int klen, int bm, int bn) {
    __shared__ float As[16][65];
    __shared__ float Bs[16][65];
    const int tid = threadIdx.x;
    const int tx = tid & 7, ty = tid >> 3;
    float acc[4][8];
#pragma unroll
    for (int i = 0; i < 4; i++)
#pragma unroll
        for (int j = 0; j < 8; j++) acc[i][j] = 0.f;

    for (int k0 = 0; k0 < klen; k0 += 16) {
        __syncthreads();
#pragma unroll
        for (int t = 0; t < 2; t++) {
            int i2 = tid + t * 128;         // 0..255
            int r = i2 >> 2, kq = i2 & 3;
            float4 a4 = *(const float4*)(A + (size_t)(bm + r) * lda + k0 + kq * 4);
            float4 b4 = *(const float4*)(Bm + (size_t)(bn + r) * ldb + k0 + kq * 4);
            As[kq * 4 + 0][r] = a4.x; As[kq * 4 + 1][r] = a4.y;
            As[kq * 4 + 2][r] = a4.z; As[kq * 4 + 3][r] = a4.w;
            Bs[kq * 4 + 0][r] = b4.x; Bs[kq * 4 + 1][r] = b4.y;
            Bs[kq * 4 + 2][r] = b4.z; Bs[kq * 4 + 3][r] = b4.w;
        }
        __syncthreads();
#pragma unroll
        for (int kk = 0; kk < 16; kk++) {
            float af[4], bf[8];
#pragma unroll
            for (int i = 0; i < 4; i++) af[i] = As[kk][ty * 4 + i];
#pragma unroll
            for (int j = 0; j < 8; j++) bf[j] = Bs[kk][tx * 8 + j];
#pragma unroll
            for (int i = 0; i < 4; i++)
#pragma unroll
                for (int j = 0; j < 8; j++) acc[i][j] += af[i] * bf[j];
        }
    }
#pragma unroll
    for (int i = 0; i < 4; i++) {
        int row = bm + ty * 4 + i;
#pragma unroll
        for (int j = 0; j < 8; j++) {
            int col = bn + tx * 8 + j;
            C[(size_t)row * ldc + col] = acc[i][j] + (bias ? bias[col] : 0.f);
        }
    }
}

// z=0: GI = yemb @ w_ih^T + b_ih (K=128); z=1: GH = h @ w_hh^T + b_hh (K=512). N=1536.
__global__ __launch_bounds__(128)
void gru_dual_k(const float* __restrict__ h_in,
                const float* __restrict__ w_ih, const float* __restrict__ w_hh,
                const float* __restrict__ b_ih, const float* __restrict__ b_hh) {
    int bm = blockIdx.y * 64, bn = blockIdx.x * 64;
    if (blockIdx.z == 0)
        sgemm64_core(g_scratch + O_YEMB, EMB_, w_ih, EMB_, b_ih, g_scratch + O_GI,
                     3 * H_, EMB_, bm, bn);
    else
        sgemm64_core(h_in, H_, w_hh, H_, b_hh, g_scratch + O_GH, 3 * H_, H_, bm, bn);
}

// z=0: DECW; z=1: DECS. A = HLAST, K=512, N=512.
__global__ __launch_bounds__(128)
void dec_dual_k(const float* __restrict__ wdw, const float* __restrict__ wdb,
                const float* __restrict__ sdw, const float* __restrict__ sdb) {
    int bm = blockIdx.y * 64, bn = blockIdx.x * 64;
    if (blockIdx.z == 0)
        sgemm64_core(g_scratch + O_HLAST, H_, wdw, H_, wdb, g_scratch + O_DECW, H_, H_, bm, bn);
    else
        sgemm64_core(g_scratch + O_HLAST, H_, sdw, H_, sdb, g_scratch + O_DECS, H_, H_, bm, bn);
}

// vd1 split-K: z = k-half (768 each). bias only in half 0. Partials summed in cvt_hid_sum.
__global__ __launch_bounds__(128)
void vd1_split_k(const float* __restrict__ w, const float* __restrict__ b) {
    int bm = blockIdx.y * 64, bn = blockIdx.x * 64;
    int z = blockIdx.z;
    sgemm64_core(g_scratch + O_CAT + z * 768, 3 * H_, w + z * 768, 3 * H_,
                 z == 0 ? b : nullptr,
                 g_scratch + (z == 0 ? O_HID : O_HID2), H_, 768, bm, bn);
}

// =====================================================================
// Pipelined HMMA feature-GEMM + score epilogue. CTA tile 128x256, 512 threads.
// grid = (2, total/128). partial[nb*total+row].
// =====================================================================
__global__ __launch_bounds__(512)
void feat_score_mma(const __nv_bfloat16* __restrict__ Ah, const __nv_bfloat16* __restrict__ Al,
                    const __nv_bfloat16* __restrict__ Bh, const __nv_bfloat16* __restrict__ Bl,
                    const float* __restrict__ dec, const float* __restrict__ cov,
                    const float* __restrict__ covproj, const float* __restrict__ v,
                    float* __restrict__ partial, int total, int Lrow) {
    extern __shared__ char smem[];
    __shared__ float sv[256], scp[256], spart[4][128];
    const uint32_t sb = smem_u32(smem);
    const int tid = threadIdx.x;
    const int lane = tid & 31, wid = tid >> 5;
    const int wm = wid & 3, wn = wid >> 2;     // wm rows (4x32), wn cols (4x64)
    const int bm = blockIdx.y * 128;
    const int nb = blockIdx.x;                 // 256-col slice
    const size_t bcol0 = (size_t)nb * 256;

    if (tid < 256) {
        sv[tid]  = v[bcol0 + tid];
        scp[tid] = covproj ? covproj[bcol0 + tid] : 0.f;
    }

    float acc[2][8][4];
#pragma unroll
    for (int mt = 0; mt < 2; mt++)
#pragma unroll
        for (int nt = 0; nt < 8; nt++)
#pragma unroll
            for (int e = 0; e < 4; e++) acc[mt][nt][e] = 0.f;

    const uint32_t a_row = (uint32_t)(wm * 32 + (lane & 15));
    const uint32_t a_koff = (uint32_t)((lane >> 4) * 16);
    const uint32_t b_row0 = (uint32_t)(wn * 64 + ((lane >> 4) & 1) * 8 + (lane & 7));
    const uint32_t b_koff = (uint32_t)(((lane >> 3) & 1) * 16);

    auto issue = [&](uint32_t stg, int ch) {
#pragma unroll
        for (int t = 0; t < 2; t++) {         // A: 1024 CP16-pairs
            int i = tid + t * 512;
            int r = i >> 3, c = i & 7;
            uint32_t dst = stg + (uint32_t)(r * RB + c * 16);
            size_t s = ((size_t)bm + r) * 512 + ch * 64 + c * 8;
            CP16(dst + FA_HI, Ah + s);
            CP16(dst + FA_LO, Al + s);
        }
#pragma unroll
        for (int t = 0; t < 4; t++) {         // B: 2048 CP16-pairs
            int i = tid + t * 512;
            int r = i >> 3, c = i & 7;
            uint32_t dst = stg + (uint32_t)(r * RB + c * 16);
            size_t s = (bcol0 + r) * 512 + ch * 64 + c * 8;
            CP16(dst + FB_HI, Bh + s);
            CP16(dst + FB_LO, Bl + s);
        }
    };

    issue(sb, 0);
    CP_COMMIT();
    for (int ch = 0; ch < 8; ch++) {
        if (ch < 7) { issue(sb + ((ch + 1) & 1) * FST, ch + 1); CP_COMMIT(); CP_WAIT(1); }
        else        { CP_WAIT(0); }
        __syncthreads();
        const uint32_t stg = sb + (ch & 1) * FST;
#pragma unroll
        for (int ks = 0; ks < 4; ks++) {
            uint32_t ah[2][4], al[2][4];
#pragma unroll
            for (int mt = 0; mt < 2; mt++) {
                uint32_t off = (a_row + mt * 16) * RB + ks * 32 + a_koff;
                ldm4(ah[mt], stg + FA_HI + off);
                ldm4(al[mt], stg + FA_LO + off);
            }
#pragma unroll
            for (int ng = 0; ng < 4; ng++) {
                uint32_t bh[4], bl[4];
                uint32_t off = (b_row0 + ng * 16) * RB + ks * 32 + b_koff;
                ldm4(bh, stg + FB_HI + off);
                ldm4(bl, stg + FB_LO + off);
#pragma unroll
                for (int mt = 0; mt < 2; mt++) {
                    mma16816(acc[mt][2 * ng],     ah[mt], &bh[0]);
                    mma16816(acc[mt][2 * ng + 1], ah[mt], &bh[2]);
                    mma16816(acc[mt][2 * ng],     ah[mt], &bl[0]);
                    mma16816(acc[mt][2 * ng + 1], ah[mt], &bl[2]);
                    mma16816(acc[mt][2 * ng],     al[mt], &bh[0]);
                    mma16816(acc[mt][2 * ng + 1], al[mt], &bh[2]);
                }
            }
        }
        __syncthreads();
    }

    // epilogue: per-row partial score over this 256-col slice
    const int g = lane >> 2, t4 = lane & 3;
#pragma unroll
    for (int mt = 0; mt < 2; mt++)
#pragma unroll
        for (int h = 0; h < 2; h++) {
            int rl = wm * 32 + mt * 16 + h * 8 + g;
            int row = bm + rl;
            int b = row / Lrow;
            float c = cov ? cov[row] : 0.f;
            const float* db = dec + (size_t)b * 512 + bcol0;
            float s = 0.f;
#pragma unroll
            for (int nt = 0; nt < 8; nt++)
#pragma unroll
                for (int e = 0; e < 2; e++) {
                    int cl = wn * 64 + nt * 8 + t4 * 2 + e;
                    float x = acc[mt][nt][h * 2 + e] + db[cl] + c * scp[cl];
                    s += sv[cl] * tanhf(x);
                }
            s += __shfl_xor_sync(0xffffffffu, s, 1);
            s += __shfl_xor_sync(0xffffffffu, s, 2);
            if (t4 == 0 && mt == 0 && h == 0) ;  // placeholder
            if (t4 == 0) {
                // accumulate across the 4 wn warps via spart
                if (wn == 0) spart[0][rl] = s;
            }
            // store per-wn partial
            if (t4 == 0) spart[wn][rl] = s;
        }
    __syncthreads();
    if (tid < 128)
        partial[(size_t)nb * total + bm + tid] =
            spart[0][tid] + spart[1][tid] + spart[2][tid] + spart[3][tid];
}

// =====================================================================
// Pipelined HMMA vocab-logits GEMM (bf16 hi/lo inputs), 256 threads, 128x128.
// =====================================================================
__global__ __launch_bounds__(256)
void vd2_mma(const __nv_bfloat16* __restrict__ Wh, const __nv_bfloat16* __restrict__ Wl,
             const __nv_bfloat16* __restrict__ Hh, const __nv_bfloat16* __restrict__ Hl,
             const float* __restrict__ bias, float* __restrict__ logits) {
    extern __shared__ char smem[];
    const uint32_t sb = smem_u32(smem);
    const int tid = threadIdx.x;
    const int lane = tid & 31, wid = tid >> 5;
    const int wm = wid & 3, wn = wid >> 2;
    const int bm = blockIdx.x * 128;

    float acc[2][8][4];
#pragma unroll
    for (int mt = 0; mt < 2; mt++)
#pragma unroll
        for (int nt = 0; nt < 8; nt++)
#pragma unroll
            for (int e = 0; e < 4; e++) acc[mt][nt][e] = 0.f;

    const uint32_t a_row = (uint32_t)(wm * 32 + (lane & 15));
    const uint32_t a_koff = (uint32_t)((lane >> 4) * 16);
    const uint32_t b_row0 = (uint32_t)(wn * 64 + ((lane >> 4) & 1) * 8 + (lane & 7));
    const uint32_t b_koff = (uint32_t)(((lane >> 3) & 1) * 16);

    auto issue_v = [&](uint32_t stg, int ch) {
        for (int i = tid; i < 1024; i += 256) {
            int r = i >> 3, c = i & 7;
            int rg = bm + r; if (rg >= V_) rg = V_ - 1;
            uint32_t dst = stg + (uint32_t)(r * RB + c * 16);
            size_t sa = (size_t)rg * 512 + ch * 64 + c * 8;
            size_t sbo = (size_t)r * 512 + ch * 64 + c * 8;
            CP16(dst + VA_HI, Wh + sa);
            CP16(dst + VA_LO, Wl + sa);
            CP16(dst + VB_HI, Hh + sbo);
            CP16(dst + VB_LO, Hl + sbo);
        }
    };

    issue_v(sb, 0);
    CP_COMMIT();
    for (int ch = 0; ch < 8; ch++) {
        if (ch < 7) { issue_v(sb + ((ch + 1) & 1) * VST, ch + 1); CP_COMMIT(); CP_WAIT(1); }
        else        { CP_WAIT(0); }
        __syncthreads();
        const uint32_t stg = sb + (ch & 1) * VST;
#pragma unroll
        for (int ks = 0; ks < 4; ks++) {
            uint32_t ah[2][4], al[2][4];
#pragma unroll
            for (int mt = 0; mt < 2; mt++) {
                uint32_t off = (a_row + mt * 16) * RB + ks * 32 + a_koff;
                ldm4(ah[mt], stg + VA_HI + off);
                ldm4(al[mt], stg + VA_LO + off);
            }
#pragma unroll
            for (int ng = 0; ng < 4; ng++) {
                uint32_t bh[4], bl[4];
                uint32_t off = (b_row0 + ng * 16) * RB + ks * 32 + b_koff;
                ldm4(bh, stg + VB_HI + off);
                ldm4(bl, stg + VB_LO + off);
#pragma unroll
                for (int mt = 0; mt < 2; mt++) {
                    mma16816(acc[mt][2 * ng],     ah[mt], &bh[0]);
                    mma16816(acc[mt][2 * ng + 1], ah[mt], &bh[2]);
                    mma16816(acc[mt][2 * ng],     ah[mt], &bl[0]);
                    mma16816(acc[mt][2 * ng + 1], ah[mt], &bl[2]);
                    mma16816(acc[mt][2 * ng],     al[mt], &bh[0]);
                    mma16816(acc[mt][2 * ng + 1], al[mt], &bh[2]);
                }
            }
        }
        __syncthreads();
    }

    // epilogue: transpose via padded smem (pad 133 -> conflict-free)
    __syncthreads();
    float* tr = (float*)smem;   // 68096 B <= VPIPE
    const int g = lane >> 2, t4 = lane & 3;
#pragma unroll
    for (int mt = 0; mt < 2; mt++)
#pragma unroll
        for (int h = 0; h < 2; h++) {
            int vl = wm * 32 + mt * 16 + h * 8 + g;
            int vg = bm + vl; int vc = vg < V_ ? vg : V_ - 1;
            float bia = bias[vc];
#pragma unroll
            for (int nt = 0; nt < 8; nt++)
#pragma unroll
                for (int e = 0; e < 2; e++) {
                    int cb = wn * 64 + nt * 8 + t4 * 2 + e;
                    tr[vl * 133 + cb] = acc[mt][nt][h * 2 + e] + bia;
                }
        }
    __syncthreads();
    for (int i = tid; i < 16384; i += 256) {
        int b = i >> 7, vl = i & 127;
        int vg = bm + vl;
        if (vg < V_) logits[(size_t)b * V_ + vg] = tr[vl * 133 + b];
    }
}

// =====================================================================
// Small kernels
// =====================================================================
__global__ void embed_k(const int* __restrict__ y, const float* __restrict__ emb) {
    int b = blockIdx.x, t = threadIdx.x;
    g_scratch[O_YEMB + b * EMB_ + t] = emb[(size_t)y[b] * EMB_ + t];
}

__global__ void gru_gate_k(const float* __restrict__ h_prev, float* __restrict__ out) {
    int idx = blockIdx.x * blockDim.x + threadIdx.x;
    int b = idx / H_, d = idx % H_;
    const float* gi = g_scratch + O_GI + b * 3 * H_;
    const float* gh = g_scratch + O_GH + b * 3 * H_;
    float r = 1.f / (1.f + expf(-(gi[d] + gh[d])));
    float z = 1.f / (1.f + expf(-(gi[H_ + d] + gh[H_ + d])));
    float n = tanhf(gi[2 * H_ + d] + r * gh[2 * H_ + d]);
    float hp = h_prev[b * H_ + d];
    float hl = (1.f - z) * n + z * hp;
    g_scratch[O_HLAST + b * H_ + d] = hl;
    g_scratch[O_CAT + b * 3 * H_ + 2 * H_ + d] = hl;
    out[OFF_H + b * H_ + d] = hl;
}

__global__ void word_softmax_k(const float* __restrict__ mask,
                               const float* __restrict__ cov_in,
                               float* __restrict__ out) {
    __shared__ float sh[512];
    int b = blockIdx.x, t = threadIdx.x;
    int idx = b * L_ + t;
    float s = -1e30f;
    if (t < L_) s = g_scratch[O_PARTW + idx] + g_scratch[O_PARTW + B_ * L_ + idx];
    sh[t] = s; __syncthreads();
    for (int o = 256; o > 0; o >>= 1) { if (t < o) sh[t] = fmaxf(sh[t], sh[t + o]); __syncthreads(); }
    float mx = sh[0]; __syncthreads();
    float e = (t < L_) ? expf(s - mx) : 0.f;
    sh[t] = e; __syncthreads();
    for (int o = 256; o > 0; o >>= 1) { if (t < o) sh[t] += sh[t + o]; __syncthreads(); }
    float sum = sh[0]; __syncthreads();
    float am = (t < L_) ? (e / sum) * mask[b * L_ + t] : 0.f;
    sh[t] = am; __syncthreads();
    for (int o = 256; o > 0; o >>= 1) { if (t < o) sh[t] += sh[t + o]; __syncthreads(); }
    float sum2 = sh[0];
    if (t < L_) {
        float a = am / (sum2 + 1e-10f);
        out[OFF_ATTN + b * L_ + t] = a;
        out[OFF_COV + b * L_ + t]  = cov_in[b * L_ + t] + a;
    }
}

__global__ void sent_softmax_k(const float* __restrict__ mask) {
    int b = blockIdx.x, t = threadIdx.x;
    int idx = b * S_ + t;
    float s = -1e30f;
    if (t < S_) s = g_scratch[O_PARTS + idx] + g_scratch[O_PARTS + B_ * S_ + idx];
    float mx = s;
#pragma unroll
    for (int o = 16; o > 0; o >>= 1) mx = fmaxf(mx, __shfl_xor_sync(0xffffffffu, mx, o));
    float e = (t < S_) ? expf(s - mx) : 0.f;
    float sum = e;
#pragma unroll
    for (int o = 16; o > 0; o >>= 1) sum += __shfl_xor_sync(0xffffffffu, sum, o);
    float am = (t < S_) ? (e / sum) * mask[b * S_ + t] : 0.f;
    float sum2 = am;
#pragma unroll
    for (int o = 16; o > 0; o >>= 1) sum2 += __shfl_xor_sync(0xffffffffu, sum2, o);
    if (t < S_) g_scratch[O_ATTNS + b * S_ + t] = am / (sum2 + 1e-10f);
}

__global__ void word_ctx_k(const float* __restrict__ mem, float* __restrict__ out) {
    __shared__ float sa[L_];
    int b = blockIdx.x, t = threadIdx.x;
    if (t < L_) sa[t] = out[OFF_ATTN + b * L_ + t];
    __syncthreads();
    float acc = 0.f;
    const float* mb = mem + (size_t)b * L_ * M_ + t;
#pragma unroll 4
    for (int l = 0; l < L_; l++) acc += sa[l] * mb[(size_t)l * M_];
    out[OFF_WCTX + b * M_ + t] = acc;
    g_scratch[O_CAT + b * 3 * H_ + t] = acc;
}

__global__ void sent_ctx_k(const float* __restrict__ mem) {
    __shared__ float sa[S_];
    int b = blockIdx.x, t = threadIdx.x;
    if (t < S_) sa[t] = g_scratch[O_ATTNS + b * S_ + t];
    __syncthreads();
    float acc = 0.f;
    const float* mb = mem + (size_t)b * S_ * M_ + t;
#pragma unroll 5
    for (int l = 0; l < S_; l++) acc += sa[l] * mb[(size_t)l * M_];
    g_scratch[O_CAT + b * 3 * H_ + H_ + t] = acc;
}

__global__ void pgen_k(const float* __restrict__ pw, const float* __restrict__ pb,
                       float* __restrict__ out) {
    __shared__ float sh[256];
    int b = blockIdx.x, t = threadIdx.x;
    float s = 0.f;
    for (int i = t; i < EMB_ + 3 * H_; i += 256) {
        float x = (i < 3 * H_) ? g_scratch[O_CAT + b * 3 * H_ + i]
                               : g_scratch[O_YEMB + b * EMB_ + (i - 3 * H_)];
        s += pw[i] * x;
    }
    sh[t] = s; __syncthreads();
    for (int o = 128; o > 0; o >>= 1) { if (t < o) sh[t] += sh[t + o]; __syncthreads(); }
    if (t == 0) {
        float p = 1.f / (1.f + expf(-(sh[0] + pb[0])));
        g_scratch[O_PGEN + b] = p;
        out[OFF_PGEN + b] = p;
    }
}

__global__ void vocab_stats_k() {
    __shared__ float sh[1024];
    int b = blockIdx.x, t = threadIdx.x;
    const float* lg = g_scratch + O_LOGITS + (size_t)b * V_;
    float m = -1e30f;
    for (int v = t; v < V_; v += 1024) m = fmaxf(m, lg[v]);
    sh[t] = m; __syncthreads();
    for (int o = 512; o > 0; o >>= 1) { if (t < o) sh[t] = fmaxf(sh[t], sh[t + o]); __syncthreads(); }
    float mx = sh[0]; __syncthreads();
    float s = 0.f;
    for (int v = t; v < V_; v += 1024) s += expf(lg[v] - mx);
    sh[t] = s; __syncthreads();
    for (int o = 512; o > 0; o >>= 1) { if (t < o) sh[t] += sh[t + o]; __syncthreads(); }
    if (t == 0) { g_scratch[O_VMAX + b] = mx; g_scratch[O_VSUM + b] = sh[0]; }
}

__global__ void assemble_k(float* __restrict__ out) {
    int b = blockIdx.y;
    int v = blockIdx.x * 1024 + threadIdx.x;
    if (v >= VX_) return;
    float r;
    if (v < V_) {
        float p = g_scratch[O_PGEN + b];
        r = p * expf(g_scratch[O_LOGITS + (size_t)b * V_ + v] - g_scratch[O_VMAX + b])
              / g_scratch[O_VSUM + b];
    } else {
        r = 0.f;
    }
    out[(size_t)b * VX_ + v] = r;
}

__global__ void scatter_k(const int* __restrict__ src_oov, float* __restrict__ out) {
    int idx = blockIdx.x * 256 + threadIdx.x;
    if (idx >= B_ * L_) return;
    int b = idx / L_;
    float val = (1.f - g_scratch[O_PGEN + b]) * out[OFF_ATTN + idx];
    atomicAdd(&out[(size_t)b * VX_ + src_oov[idx]], val);
}

// =====================================================================
extern "C" void kernel_launch(void* const* d_in, const int* in_sizes, int n_in,
                              void* d_out, int out_size) {
    const float* h_in      = (const float*)d_in[0];
    const float* wmem      = (const float*)d_in[1];
    const float* smemb     = (const float*)d_in[2];
    const float* wmask     = (const float*)d_in[3];
    const float* smask     = (const float*)d_in[4];
    const float* coverage  = (const float*)d_in[5];
    const float* emb       = (const float*)d_in[6];
    const float* gru_w_ih  = (const float*)d_in[7];
    const float* gru_w_hh  = (const float*)d_in[8];
    const float* gru_b_ih  = (const float*)d_in[9];
    const float* gru_b_hh  = (const float*)d_in[10];
    const float* w_mem_proj= (const float*)d_in[11];
    const float* w_dec_w   = (const float*)d_in[12];
    const float* w_dec_b   = (const float*)d_in[13];
    const float* w_v       = (const float*)d_in[14];
    const float* w_covp    = (const float*)d_in[15];
    const float* s_mem_proj= (const float*)d_in[16];
    const float* s_dec_w   = (const float*)d_in[17];
    const float* s_dec_b   = (const float*)d_in[18];
    const float* s_v       = (const float*)d_in[19];
    const float* pgen_w    = (const float*)d_in[20];
    const float* pgen_b    = (const float*)d_in[21];
    const float* vd1_w     = (const float*)d_in[22];
    const float* vd1_b     = (const float*)d_in[23];
    const float* vd2_w     = (const float*)d_in[24];
    const float* vd2_b     = (const float*)d_in[25];
    const int*   y         = (const int*)d_in[26];
    const int*   src_oov   = (const int*)d_in[27];
    float* out = (float*)d_out;

    float* sp = nullptr;
    cudaGetSymbolAddress((void**)&sp, g_scratch);
    __nv_bfloat16* bp = nullptr;
    cudaGetSymbolAddress((void**)&bp, g_bf);

    static bool attr_done = false;
    if (!attr_done) {
        cudaFuncSetAttribute(feat_score_mma, cudaFuncAttributeMaxDynamicSharedMemorySize, FPIPE);
        cudaFuncSetAttribute(vd2_mma,        cudaFuncAttributeMaxDynamicSharedMemorySize, VPIPE);
        attr_done = true;
    }

    // 0. pre-convert big operands to bf16 hi/lo
    cvt_k<<<(B_*L_*512/4 + 255)/256, 256>>>(wmem,       bp + BF_WQH, bp + BF_WQL, B_*L_*512/4);
    cvt_k<<<(B_*S_*512/4 + 255)/256, 256>>>(smemb,      bp + BF_SBH, bp + BF_SBL, B_*S_*512/4);
    cvt_k<<<(512*512/4   + 255)/256, 256>>>(w_mem_proj, bp + BF_WPH, bp + BF_WPL, 512*512/4);
    cvt_k<<<(512*512/4   + 255)/256, 256>>>(s_mem_proj, bp + BF_SPH, bp + BF_SPL, 512*512/4);
    cvt_k<<<(V_*512/4    + 255)/256, 256>>>(vd2_w,      bp + BF_VWH, bp + BF_VWL, V_*512/4);

    // 1. embedding gather
    embed_k<<<B_, EMB_>>>(y, emb);
    // 2. GRU input & hidden GEMMs (one launch, z=2)
    gru_dual_k<<<dim3(24, 2, 2), 128>>>(h_in, gru_w_ih, gru_w_hh, gru_b_ih, gru_b_hh);
    // 3. GRU gates
    gru_gate_k<<<(B_ * H_) / 256, 256>>>(h_in, out);
    // 4. decoder projections (one launch, z=2)
    dec_dual_k<<<dim3(8, 2, 2), 128>>>(w_dec_w, w_dec_b, s_dec_w, s_dec_b);
    // 5/6. pipelined HMMA fused feature GEMM + score epilogue
    feat_score_mma<<<dim3(2, (B_ * L_) / 128), 512, FPIPE>>>(
        bp + BF_WQH, bp + BF_WQL, bp + BF_WPH, bp + BF_WPL,
        sp + O_DECW, coverage, w_covp, w_v, sp + O_PARTW, B_ * L_, L_);
    feat_score_mma<<<dim3(2, (B_ * S_) / 128), 512, FPIPE>>>(
        bp + BF_SBH, bp + BF_SBL, bp + BF_SPH, bp + BF_SPL,
        sp + O_DECS, nullptr, nullptr, s_v, sp + O_PARTS, B_ * S_, S_);
    // 7/8. masked softmaxes
    word_softmax_k<<<B_, 512>>>(wmask, coverage, out);
    sent_softmax_k<<<B_, 32>>>(smask);
    // 9/10. contexts
    word_ctx_k<<<B_, 512>>>(wmem, out);
    sent_ctx_k<<<B_, 512>>>(smemb);
    // 11. vd1 split-K (z=2) then sum+convert hid
    vd1_split_k<<<dim3(8, 2, 2), 128>>>(vd1_w, vd1_b);
    cvt_hid_sum<<<(B_*H_/4 + 255)/256, 256>>>(sp + O_HID, sp + O_HID2,
                                              bp + BF_HIH, bp + BF_HIL, B_*H_/4);
    // 12. vocab logits (pipelined HMMA)
    vd2_mma<<<(V_ + 127) / 128, 256, VPIPE>>>(bp + BF_VWH, bp + BF_VWL,
                                              bp + BF_HIH, bp + BF_HIL, vd2_b, sp + O_LOGITS);
    // 13. vocab softmax stats
    vocab_stats_k<<<B_, 1024>>>();
    // 14. p_gen
    pgen_k<<<B_, 256>>>(pgen_w, pgen_b, out);
    // 15. final_dist base
    assemble_k<<<dim3((VX_ + 1023) / 1024, B_), 1024>>>(out);
    // 16. scatter-add copy distribution
    scatter_k<<<(B_ * L_ + 255) / 256, 256>>>(src_oov, out);
}